// round 7
// baseline (speedup 1.0000x reference)
#include <cuda_runtime.h>
#include <math.h>
#include <stdint.h>

// Problem constants
#define LAYERS 8
#define BATCH  256
#define TIME   8
#define EDIM   1024
#define HDIM   1024

#define BM     64
#define BK     32
#define KT     32      // 1024 / BK
#define STAGES 3

// Scratch buffers
__device__ float g_buf0[BATCH * TIME * HDIM];            // layer outputs (B,T,H)
__device__ float g_buf1[BATCH * TIME * HDIM];
__device__ float g_crun[BATCH * HDIM];                   // running cell state
__device__ float g_pre[(size_t)BATCH * TIME * 4 * HDIM]; // x-part gate preacts

__device__ __forceinline__ uint32_t f2tf32(float f) {
    uint32_t r;
    asm("cvt.rna.tf32.f32 %0, %1;" : "=r"(r) : "f"(f));
    return r;
}

__device__ __forceinline__ void mma_tf32(float c[4],
                                         uint32_t a0, uint32_t a1, uint32_t a2, uint32_t a3,
                                         uint32_t b0, uint32_t b1) {
    asm volatile(
        "mma.sync.aligned.m16n8k8.row.col.f32.tf32.tf32.f32 "
        "{%0,%1,%2,%3}, {%4,%5,%6,%7}, {%8,%9}, {%0,%1,%2,%3};"
        : "+f"(c[0]), "+f"(c[1]), "+f"(c[2]), "+f"(c[3])
        : "r"(a0), "r"(a1), "r"(a2), "r"(a3), "r"(b0), "r"(b1));
}

__device__ __forceinline__ void cp16(float* dst, const float* src) {
    uint32_t d = (uint32_t)__cvta_generic_to_shared(dst);
    asm volatile("cp.async.cg.shared.global [%0], [%1], 16;" :: "r"(d), "l"(src));
}
__device__ __forceinline__ void cp_commit() {
    asm volatile("cp.async.commit_group;");
}
template <int N> __device__ __forceinline__ void cp_wait() {
    asm volatile("cp.async.wait_group %0;" :: "n"(N));
}

// -----------------------------------------------------------------------------
// GEMM mainloop: acc += A[r0:r0+64, 0:1024] @ [Wu|Wf|Wo|Wc][0:1024, j0:j0+BJG]
// A tile: 64x32 floats, XOR-swizzled (seg ^= row&7), stride 32 (conflict-free).
// B tile: [4*32][BSTR] padded rows (BSTR=24 for BJG=16, 40 for BJG=32).
// Single __syncthreads per K-iteration (issue placed after the barrier).
// -----------------------------------------------------------------------------
template <int BJG>
__device__ __forceinline__ void gemm_main(
    float* smem,
    const float* __restrict__ Aptr, int strideA, int r0,
    const float* __restrict__ Wu, const float* __restrict__ Wf,
    const float* __restrict__ Wo, const float* __restrict__ Wc,
    int j0, float acc[2][BJG / 8][4])
{
    constexpr int NI      = BJG / 8;
    constexpr int BSTR    = (BJG == 32) ? 40 : 24;
    constexpr int A_F     = 64 * 32;
    constexpr int STAGE_F = A_F + 4 * 32 * BSTR;

    const int tid  = threadIdx.x;
    const int lane = tid & 31;
    const int warp = tid >> 5;
    const int wy   = warp >> 2;       // row half
    const int wx   = warp & 3;        // gate
    const int g4   = lane >> 2;
    const int t4   = lane & 3;

    // A cp.async mapping: 64 rows x 8 segs(16B); 2 segs/thread
    const int aRow = tid >> 2;
    const int aSeg = tid & 3;
    const int aSw0 = ((aSeg)     ^ (aRow & 7)) * 4;
    const int aSw1 = ((aSeg + 4) ^ (aRow & 7)) * 4;
    const float* aSrc = Aptr + (size_t)(r0 + aRow) * strideA;

    // B cp.async mapping: 128 (gate,krow) rows x NI/2*... NI segs per thread
    const int grow    = tid >> 1;            // 0..127 = gate*32 + krow
    const int gate    = grow >> 5;
    const int krow    = grow & 31;
    const int segBase = (tid & 1) * NI;
    const float* Wsel = (gate == 0) ? Wu : (gate == 1) ? Wf : (gate == 2) ? Wo : Wc;
    const float* wSrc = Wsel + (size_t)krow * HDIM + j0 + segBase * 4;

    auto issue = [&](int c) {
        float* sA = smem + (c % STAGES) * STAGE_F;
        float* sB = sA + A_F;
        const int k0 = c * BK;
        cp16(sA + aRow * 32 + aSw0, aSrc + k0 + aSeg * 4);
        cp16(sA + aRow * 32 + aSw1, aSrc + k0 + (aSeg + 4) * 4);
        const float* ws = wSrc + (size_t)k0 * HDIM;
        float* wd = sB + grow * BSTR + segBase * 4;
        #pragma unroll
        for (int s = 0; s < NI; s++) cp16(wd + s * 4, ws + s * 4);
        cp_commit();
    };

    auto compute = [&](int slot) {
        const float* sA = smem + slot * STAGE_F;
        const float* sB = sA + A_F + wx * (32 * BSTR);
        #pragma unroll
        for (int q = 0; q < 4; q++) {
            uint32_t a[2][4];
            #pragma unroll
            for (int mi = 0; mi < 2; mi++) {
                const float* pa = sA + (32 * wy + 16 * mi + g4) * 32 + t4;
                a[mi][0] = f2tf32(pa[((2 * q)     ^ g4) * 4]);
                a[mi][1] = f2tf32(pa[256 + (((2 * q))     ^ g4) * 4]);
                a[mi][2] = f2tf32(pa[((2 * q + 1) ^ g4) * 4]);
                a[mi][3] = f2tf32(pa[256 + (((2 * q + 1)) ^ g4) * 4]);
            }
            const int kr = 8 * q + t4;
            #pragma unroll
            for (int ni = 0; ni < NI; ni++) {
                const int col = 8 * ni + g4;
                const uint32_t b0 = f2tf32(sB[kr * BSTR + col]);
                const uint32_t b1 = f2tf32(sB[(kr + 4) * BSTR + col]);
                mma_tf32(acc[0][ni], a[0][0], a[0][1], a[0][2], a[0][3], b0, b1);
                mma_tf32(acc[1][ni], a[1][0], a[1][1], a[1][2], a[1][3], b0, b1);
            }
        }
    };

    issue(0);
    issue(1);
    #pragma unroll 1
    for (int c = 0; c < KT; c++) {
        cp_wait<STAGES - 2>();       // stage c arrived (this thread's groups)
        __syncthreads();             // publish arrivals + protect slot reuse
        if (c + 2 < KT) issue(c + 2); else cp_commit();
        compute(c % STAGES);
    }
}

// ---------------------------------------------------------------------------
// Pre-kernel: x-part GEMM for a whole layer (rows r = b*T + t).
// ---------------------------------------------------------------------------
__global__ __launch_bounds__(256)
void lstm_pre(const float* __restrict__ A, int strideA,
              const float* __restrict__ Wu, const float* __restrict__ Wf,
              const float* __restrict__ Wo, const float* __restrict__ Wc,
              float* __restrict__ Gpre)
{
    extern __shared__ float smem[];
    const int j0 = blockIdx.x * 32;
    const int r0 = blockIdx.y * BM;

    float acc[2][4][4];
    #pragma unroll
    for (int mi = 0; mi < 2; mi++)
        #pragma unroll
        for (int ni = 0; ni < 4; ni++)
            #pragma unroll
            for (int r = 0; r < 4; r++) acc[mi][ni][r] = 0.0f;

    gemm_main<32>(smem, A, strideA, r0, Wu, Wf, Wo, Wc, j0, acc);

    const int lane = threadIdx.x & 31;
    const int warp = threadIdx.x >> 5;
    const int wy = warp >> 2, wx = warp & 3;
    const int g4 = lane >> 2, t4 = lane & 3;

    #pragma unroll
    for (int mi = 0; mi < 2; mi++) {
        #pragma unroll
        for (int ni = 0; ni < 4; ni++) {
            const int row = r0 + 32 * wy + 16 * mi + g4;
            const int col = j0 + 8 * ni + 2 * t4;
            *(float2*)(Gpre + ((size_t)row * 4 + wx) * HDIM + col) =
                make_float2(acc[mi][ni][0], acc[mi][ni][1]);
            *(float2*)(Gpre + ((size_t)(row + 8) * 4 + wx) * HDIM + col) =
                make_float2(acc[mi][ni][2], acc[mi][ni][3]);
        }
    }
}

// ---------------------------------------------------------------------------
// Step kernel: h-recurrent GEMM (K=1024, 64x64 tile) + fused LSTM cell update.
// ---------------------------------------------------------------------------
#define GS_STRIDE 66

__global__ __launch_bounds__(256)
void lstm_step(const float* __restrict__ hbase, int hstride,
               const float* __restrict__ Wu, const float* __restrict__ Wf,
               const float* __restrict__ Wo, const float* __restrict__ Wc,
               const float* __restrict__ bu, const float* __restrict__ bf,
               const float* __restrict__ bo, const float* __restrict__ bc,
               const float* __restrict__ Gpre, int t,
               const float* __restrict__ c_old_src,
               float* __restrict__ c_run,
               float* __restrict__ hrow,              // row stride T*H
               float* __restrict__ crow,              // or null
               float* __restrict__ outHt, float* __restrict__ outCt)
{
    extern __shared__ float smem[];
    const int j0 = blockIdx.x * 16;
    const int b0 = blockIdx.y * BM;

    float acc[2][2][4];
    #pragma unroll
    for (int mi = 0; mi < 2; mi++)
        #pragma unroll
        for (int ni = 0; ni < 2; ni++)
            #pragma unroll
            for (int r = 0; r < 4; r++) acc[mi][ni][r] = 0.0f;

    gemm_main<16>(smem, hbase, hstride, b0, Wu, Wf, Wo, Wc, j0, acc);

    cp_wait<0>();
    __syncthreads();

    // Gate exchange through smem: 64 rows x (4 gates x 16 cols)
    float* gs = smem;
    {
        const int lane = threadIdx.x & 31;
        const int warp = threadIdx.x >> 5;
        const int wy = warp >> 2, wx = warp & 3;
        const int g4 = lane >> 2, t4 = lane & 3;
        #pragma unroll
        for (int mi = 0; mi < 2; mi++) {
            #pragma unroll
            for (int ni = 0; ni < 2; ni++) {
                const int row = 32 * wy + 16 * mi + g4;
                const int col = wx * 16 + 8 * ni + 2 * t4;
                *(float2*)(gs + row * GS_STRIDE + col) =
                    make_float2(acc[mi][ni][0], acc[mi][ni][1]);
                *(float2*)(gs + (row + 8) * GS_STRIDE + col) =
                    make_float2(acc[mi][ni][2], acc[mi][ni][3]);
            }
        }
    }
    __syncthreads();

    const int jj   = threadIdx.x & 15;
    const int rgrp = threadIdx.x >> 4;    // 0..15
    const int j    = j0 + jj;
    const float b_u = bu[j], b_f = bf[j], b_o = bo[j], b_c = bc[j];

    #pragma unroll
    for (int i = 0; i < 4; i++) {
        const int row = rgrp + 16 * i;
        const int b   = b0 + row;
        const size_t gbase = ((size_t)(b * TIME + t) * 4) * HDIM + j;
        const float su = gs[row * GS_STRIDE +      jj] + Gpre[gbase]            + b_u;
        const float sf = gs[row * GS_STRIDE + 16 + jj] + Gpre[gbase +     HDIM] + b_f;
        const float so = gs[row * GS_STRIDE + 32 + jj] + Gpre[gbase + 2 * HDIM] + b_o;
        const float sc = gs[row * GS_STRIDE + 48 + jj] + Gpre[gbase + 3 * HDIM] + b_c;
        const float u  = 1.0f / (1.0f + expf(-su));
        const float f  = 1.0f / (1.0f + expf(-sf));
        const float o  = 1.0f / (1.0f + expf(-so));
        const float ct = tanhf(sc);
        const size_t idx = (size_t)b * HDIM + j;
        const float c_new = f * c_old_src[idx] + u * ct;
        const float h_new = o * tanhf(c_new);
        c_run[idx] = c_new;
        hrow[(size_t)b * (TIME * HDIM) + j] = h_new;
        if (crow) crow[(size_t)b * (TIME * HDIM) + j] = c_new;
        if (outHt) { outHt[idx] = h_new; outCt[idx] = c_new; }
    }
}

extern "C" void kernel_launch(void* const* d_in, const int* in_sizes, int n_in,
                              void* d_out, int out_size) {
    const float* x  = (const float*)d_in[0];   // (B, T, E)
    const float* h0 = (const float*)d_in[1];   // (L, B, H)
    const float* c0 = (const float*)d_in[2];   // (L, B, H)
    const float* Wu = (const float*)d_in[3];   // (L, 2048, H)
    const float* bu = (const float*)d_in[4];   // (L, H)
    const float* Wf = (const float*)d_in[5];
    const float* bf = (const float*)d_in[6];
    const float* Wo = (const float*)d_in[7];
    const float* bo = (const float*)d_in[8];
    const float* Wc = (const float*)d_in[9];
    const float* bc = (const float*)d_in[10];

    float* out = (float*)d_out;
    float* outHidden = out;                                   // (B, T, H)
    float* outMem    = out + (size_t)BATCH * TIME * HDIM;     // (B, T, H)
    float* outHt     = out + (size_t)2 * BATCH * TIME * HDIM; // (B, 1, H)
    float* outCt     = outHt + (size_t)BATCH * HDIM;          // (B, 1, H)

    float *buf0, *buf1, *crun, *gpre;
    cudaGetSymbolAddress((void**)&buf0, g_buf0);
    cudaGetSymbolAddress((void**)&buf1, g_buf1);
    cudaGetSymbolAddress((void**)&crun, g_crun);
    cudaGetSymbolAddress((void**)&gpre, g_pre);

    // Dynamic smem: pre = 3*(2048 + 4*32*40)*4 = 86016 B, step = 3*(2048 + 4*32*24)*4 = 61440 B
    const int PRE_SMEM  = STAGES * (64 * 32 + 4 * 32 * 40) * 4;
    const int STEP_SMEM = STAGES * (64 * 32 + 4 * 32 * 24) * 4;
    cudaFuncSetAttribute(lstm_pre,  cudaFuncAttributeMaxDynamicSharedMemorySize, PRE_SMEM);
    cudaFuncSetAttribute(lstm_step, cudaFuncAttributeMaxDynamicSharedMemorySize, STEP_SMEM);

    const dim3 blk(256);
    const dim3 gridPre(HDIM / 32, (BATCH * TIME) / BM);  // (32, 32) = 1024 blocks
    const dim3 gridStep(HDIM / 16, BATCH / BM);          // (64, 4)  = 256 blocks

    for (int l = 0; l < LAYERS; l++) {
        const size_t wOff = (size_t)l * 2048 * HDIM;
        const size_t bOff = (size_t)l * HDIM;
        const float* Wu_l = Wu + wOff;
        const float* Wf_l = Wf + wOff;
        const float* Wo_l = Wo + wOff;
        const float* Wc_l = Wc + wOff;

        const float* Aprev;
        int strideA;
        if (l == 0) { Aprev = x; strideA = EDIM; }
        else { Aprev = ((l - 1) & 1) ? buf1 : buf0; strideA = HDIM; }
        float* cur = (l == LAYERS - 1) ? outHidden : ((l & 1) ? buf1 : buf0);
        const bool last = (l == LAYERS - 1);

        lstm_pre<<<gridPre, blk, PRE_SMEM>>>(Aprev, strideA,
                                             Wu_l, Wf_l, Wo_l, Wc_l, gpre);

        const float* Wu_h = Wu_l + (size_t)EDIM * HDIM;
        const float* Wf_h = Wf_l + (size_t)EDIM * HDIM;
        const float* Wo_h = Wo_l + (size_t)EDIM * HDIM;
        const float* Wc_h = Wc_l + (size_t)EDIM * HDIM;

        for (int t = 0; t < TIME; t++) {
            const float* hbase;
            int hstride;
            if (t == 0) { hbase = h0 + (size_t)l * BATCH * HDIM; hstride = HDIM; }
            else        { hbase = cur + (size_t)(t - 1) * HDIM;  hstride = TIME * HDIM; }
            const float* coldsrc = (t == 0) ? (c0 + (size_t)l * BATCH * HDIM) : crun;
            float* hrow = cur + (size_t)t * HDIM;
            float* crow = last ? (outMem + (size_t)t * HDIM) : nullptr;
            float* oHt  = (last && t == TIME - 1) ? outHt : nullptr;
            float* oCt  = (last && t == TIME - 1) ? outCt : nullptr;

            lstm_step<<<gridStep, blk, STEP_SMEM>>>(hbase, hstride,
                                                    Wu_h, Wf_h, Wo_h, Wc_h,
                                                    bu + bOff, bf + bOff, bo + bOff, bc + bOff,
                                                    gpre, t, coldsrc, crun, hrow, crow, oHt, oCt);
        }
    }
}

// round 9
// speedup vs baseline: 1.6059x; 1.6059x over previous
#include <cuda_runtime.h>
#include <math.h>
#include <stdint.h>

// Problem constants
#define LAYERS 8
#define BATCH  256
#define TIME   8
#define EDIM   1024
#define HDIM   1024

#define BM     64
#define BK     32
#define KT     32      // 1024 / BK
#define STAGES 3

// Scratch buffers
__device__ float g_buf0[BATCH * TIME * HDIM];            // layer outputs, tf32-rounded (B,T,H)
__device__ float g_buf1[BATCH * TIME * HDIM];
__device__ float g_crun[BATCH * HDIM];                   // running cell state (exact fp32)
__device__ float g_pre[(size_t)BATCH * TIME * 4 * HDIM]; // x-part gate preacts (exact fp32)
// Pre-rounded MMA operands
__device__ float g_wr[(size_t)4 * LAYERS * 2048 * HDIM]; // [gate][l][k][j], 268 MB
__device__ float g_xr[BATCH * TIME * EDIM];              // rounded x
__device__ float g_h0r[LAYERS * BATCH * HDIM];           // rounded h0

__device__ __forceinline__ float f2tf32f(float f) {
    float r;
    asm("{ .reg .b32 t; cvt.rna.tf32.f32 t, %1; mov.b32 %0, t; }" : "=f"(r) : "f"(f));
    return r;
}

__device__ __forceinline__ void mma_tf32(float c[4],
                                         uint32_t a0, uint32_t a1, uint32_t a2, uint32_t a3,
                                         uint32_t b0, uint32_t b1) {
    asm volatile(
        "mma.sync.aligned.m16n8k8.row.col.f32.tf32.tf32.f32 "
        "{%0,%1,%2,%3}, {%4,%5,%6,%7}, {%8,%9}, {%0,%1,%2,%3};"
        : "+f"(c[0]), "+f"(c[1]), "+f"(c[2]), "+f"(c[3])
        : "r"(a0), "r"(a1), "r"(a2), "r"(a3), "r"(b0), "r"(b1));
}

__device__ __forceinline__ void cp16(float* dst, const float* src) {
    uint32_t d = (uint32_t)__cvta_generic_to_shared(dst);
    asm volatile("cp.async.cg.shared.global [%0], [%1], 16;" :: "r"(d), "l"(src));
}
__device__ __forceinline__ void cp_commit() {
    asm volatile("cp.async.commit_group;");
}
template <int N> __device__ __forceinline__ void cp_wait() {
    asm volatile("cp.async.wait_group %0;" :: "n"(N));
}

// ---------------------------------------------------------------------------
// Prep: elementwise round-to-nearest tf32 copy (float4 grid-stride).
// ---------------------------------------------------------------------------
__global__ __launch_bounds__(256)
void prep_round(const float4* __restrict__ src, float4* __restrict__ dst, size_t n4) {
    size_t i = (size_t)blockIdx.x * blockDim.x + threadIdx.x;
    const size_t stride = (size_t)gridDim.x * blockDim.x;
    for (; i < n4; i += stride) {
        float4 v = src[i];
        v.x = f2tf32f(v.x); v.y = f2tf32f(v.y);
        v.z = f2tf32f(v.z); v.w = f2tf32f(v.w);
        dst[i] = v;
    }
}

// -----------------------------------------------------------------------------
// GEMM mainloop: acc += A[r0:r0+64, 0:1024] @ [Wu|Wf|Wo|Wc][0:1024, j0:j0+32]
// All operands pre-rounded to tf32 grid -> raw bit loads, zero cvt in loop.
// A tile: 64x32 floats, XOR-swizzled (seg ^= row&7), stride 32 (conflict-free).
// B tile: [4*32][40] padded rows. Single __syncthreads per K-iteration.
// -----------------------------------------------------------------------------
#define BSTR    40
#define A_F     (64 * 32)
#define STAGE_F (A_F + 4 * 32 * BSTR)   // 2048 + 5120 = 7168 floats

__device__ __forceinline__ void gemm_main(
    float* smem,
    const float* __restrict__ Aptr, int strideA, int r0,
    const float* __restrict__ Wu, const float* __restrict__ Wf,
    const float* __restrict__ Wo, const float* __restrict__ Wc,
    int j0, float acc[2][4][4])
{
    const int tid  = threadIdx.x;
    const int lane = tid & 31;
    const int warp = tid >> 5;
    const int wy   = warp >> 2;       // row half
    const int wx   = warp & 3;        // gate
    const int g4   = lane >> 2;
    const int t4   = lane & 3;

    // A cp.async mapping: 64 rows x 8 segs(16B); 2 segs/thread
    const int aRow = tid >> 2;
    const int aSeg = tid & 3;
    const int aSw0 = ((aSeg)     ^ (aRow & 7)) * 4;
    const int aSw1 = ((aSeg + 4) ^ (aRow & 7)) * 4;
    const float* aSrc = Aptr + (size_t)(r0 + aRow) * strideA;

    // B cp.async mapping: 128 (gate,krow) rows x 8 segs; 4 segs/thread
    const int grow    = tid >> 1;            // 0..127 = gate*32 + krow
    const int gate    = grow >> 5;
    const int krow    = grow & 31;
    const int segBase = (tid & 1) * 4;
    const float* Wsel = (gate == 0) ? Wu : (gate == 1) ? Wf : (gate == 2) ? Wo : Wc;
    const float* wSrc = Wsel + (size_t)krow * HDIM + j0 + segBase * 4;

    auto issue = [&](int c) {
        float* sA = smem + (c % STAGES) * STAGE_F;
        float* sB = sA + A_F;
        const int k0 = c * BK;
        cp16(sA + aRow * 32 + aSw0, aSrc + k0 + aSeg * 4);
        cp16(sA + aRow * 32 + aSw1, aSrc + k0 + (aSeg + 4) * 4);
        const float* ws = wSrc + (size_t)k0 * HDIM;
        float* wd = sB + grow * BSTR + segBase * 4;
        #pragma unroll
        for (int s = 0; s < 4; s++) cp16(wd + s * 4, ws + s * 4);
        cp_commit();
    };

    auto compute = [&](int slot) {
        const float* sA = smem + slot * STAGE_F;
        const float* sB = sA + A_F + wx * (32 * BSTR);
        #pragma unroll
        for (int q = 0; q < 4; q++) {
            uint32_t a[2][4];
            #pragma unroll
            for (int mi = 0; mi < 2; mi++) {
                const float* pa = sA + (32 * wy + 16 * mi + g4) * 32 + t4;
                a[mi][0] = __float_as_uint(pa[((2 * q)     ^ g4) * 4]);
                a[mi][1] = __float_as_uint(pa[256 + ((2 * q)     ^ g4) * 4]);
                a[mi][2] = __float_as_uint(pa[((2 * q + 1) ^ g4) * 4]);
                a[mi][3] = __float_as_uint(pa[256 + ((2 * q + 1) ^ g4) * 4]);
            }
            const int kr = 8 * q + t4;
            #pragma unroll
            for (int ni = 0; ni < 4; ni++) {
                const int col = 8 * ni + g4;
                const uint32_t b0 = __float_as_uint(sB[kr * BSTR + col]);
                const uint32_t b1 = __float_as_uint(sB[(kr + 4) * BSTR + col]);
                mma_tf32(acc[0][ni], a[0][0], a[0][1], a[0][2], a[0][3], b0, b1);
                mma_tf32(acc[1][ni], a[1][0], a[1][1], a[1][2], a[1][3], b0, b1);
            }
        }
    };

    issue(0);
    issue(1);
    #pragma unroll 1
    for (int c = 0; c < KT; c++) {
        cp_wait<STAGES - 2>();       // stage c's groups complete (this thread)
        __syncthreads();             // publish arrivals + protect slot reuse
        if (c + 2 < KT) issue(c + 2); else cp_commit();
        compute(c % STAGES);
    }
}

// ---------------------------------------------------------------------------
// Pre-kernel: x-part GEMM for a whole layer (rows r = b*T + t).
// ---------------------------------------------------------------------------
__global__ __launch_bounds__(256)
void lstm_pre(const float* __restrict__ A, int strideA,
              const float* __restrict__ Wu, const float* __restrict__ Wf,
              const float* __restrict__ Wo, const float* __restrict__ Wc,
              float* __restrict__ Gpre)
{
    extern __shared__ float smem[];
    const int j0 = blockIdx.x * 32;
    const int r0 = blockIdx.y * BM;

    float acc[2][4][4];
    #pragma unroll
    for (int mi = 0; mi < 2; mi++)
        #pragma unroll
        for (int ni = 0; ni < 4; ni++)
            #pragma unroll
            for (int r = 0; r < 4; r++) acc[mi][ni][r] = 0.0f;

    gemm_main(smem, A, strideA, r0, Wu, Wf, Wo, Wc, j0, acc);

    const int lane = threadIdx.x & 31;
    const int warp = threadIdx.x >> 5;
    const int wy = warp >> 2, wx = warp & 3;
    const int g4 = lane >> 2, t4 = lane & 3;

    #pragma unroll
    for (int mi = 0; mi < 2; mi++) {
        #pragma unroll
        for (int ni = 0; ni < 4; ni++) {
            const int row = r0 + 32 * wy + 16 * mi + g4;
            const int col = j0 + 8 * ni + 2 * t4;
            *(float2*)(Gpre + ((size_t)row * 4 + wx) * HDIM + col) =
                make_float2(acc[mi][ni][0], acc[mi][ni][1]);
            *(float2*)(Gpre + ((size_t)(row + 8) * 4 + wx) * HDIM + col) =
                make_float2(acc[mi][ni][2], acc[mi][ni][3]);
        }
    }
}

// ---------------------------------------------------------------------------
// Step kernel: h-recurrent GEMM (K=1024, 64x128 tile) + fused LSTM cell update.
// Writes rounded h into the recurrence buffer; exact values into outputs.
// ---------------------------------------------------------------------------
#define GS_STRIDE 130

__global__ __launch_bounds__(256)
void lstm_step(const float* __restrict__ hbase, int hstride,
               const float* __restrict__ Wu, const float* __restrict__ Wf,
               const float* __restrict__ Wo, const float* __restrict__ Wc,
               const float* __restrict__ bu, const float* __restrict__ bf,
               const float* __restrict__ bo, const float* __restrict__ bc,
               const float* __restrict__ Gpre, int t,
               const float* __restrict__ c_old_src,
               float* __restrict__ c_run,
               float* __restrict__ hrow,              // rounded h, buf, stride T*H
               float* __restrict__ hexact,            // outHidden row or null
               float* __restrict__ crow,              // outMem row or null
               float* __restrict__ outHt, float* __restrict__ outCt)
{
    extern __shared__ float smem[];
    const int j0 = blockIdx.x * 32;
    const int b0 = blockIdx.y * BM;

    float acc[2][4][4];
    #pragma unroll
    for (int mi = 0; mi < 2; mi++)
        #pragma unroll
        for (int ni = 0; ni < 4; ni++)
            #pragma unroll
            for (int r = 0; r < 4; r++) acc[mi][ni][r] = 0.0f;

    gemm_main(smem, hbase, hstride, b0, Wu, Wf, Wo, Wc, j0, acc);

    cp_wait<0>();
    __syncthreads();

    // Gate exchange through smem: 64 rows x (4 gates x 32 cols)
    float* gs = smem;
    {
        const int lane = threadIdx.x & 31;
        const int warp = threadIdx.x >> 5;
        const int wy = warp >> 2, wx = warp & 3;
        const int g4 = lane >> 2, t4 = lane & 3;
        #pragma unroll
        for (int mi = 0; mi < 2; mi++) {
            #pragma unroll
            for (int ni = 0; ni < 4; ni++) {
                const int row = 32 * wy + 16 * mi + g4;
                const int col = wx * 32 + 8 * ni + 2 * t4;
                *(float2*)(gs + row * GS_STRIDE + col) =
                    make_float2(acc[mi][ni][0], acc[mi][ni][1]);
                *(float2*)(gs + (row + 8) * GS_STRIDE + col) =
                    make_float2(acc[mi][ni][2], acc[mi][ni][3]);
            }
        }
    }
    __syncthreads();

    const int jj = threadIdx.x & 31;
    const int r0 = threadIdx.x >> 5;
    const int j  = j0 + jj;
    const float b_u = bu[j], b_f = bf[j], b_o = bo[j], b_c = bc[j];

    #pragma unroll
    for (int i = 0; i < 8; i++) {
        const int row = r0 + 8 * i;
        const int b   = b0 + row;
        const size_t gbase = ((size_t)(b * TIME + t) * 4) * HDIM + j;
        const float su = gs[row * GS_STRIDE +      jj] + Gpre[gbase]            + b_u;
        const float sf = gs[row * GS_STRIDE + 32 + jj] + Gpre[gbase +     HDIM] + b_f;
        const float so = gs[row * GS_STRIDE + 64 + jj] + Gpre[gbase + 2 * HDIM] + b_o;
        const float sc = gs[row * GS_STRIDE + 96 + jj] + Gpre[gbase + 3 * HDIM] + b_c;
        const float u  = 1.0f / (1.0f + expf(-su));
        const float f  = 1.0f / (1.0f + expf(-sf));
        const float o  = 1.0f / (1.0f + expf(-so));
        const float ct = tanhf(sc);
        const size_t idx = (size_t)b * HDIM + j;
        const float c_new = f * c_old_src[idx] + u * ct;
        const float h_new = o * tanhf(c_new);
        c_run[idx] = c_new;
        const size_t ridx = (size_t)b * (TIME * HDIM) + j;
        hrow[ridx] = f2tf32f(h_new);          // rounded: GEMM input only
        if (hexact) { hexact[ridx] = h_new; crow[ridx] = c_new; }
        if (outHt) { outHt[idx] = h_new; outCt[idx] = c_new; }
    }
}

extern "C" void kernel_launch(void* const* d_in, const int* in_sizes, int n_in,
                              void* d_out, int out_size) {
    const float* x  = (const float*)d_in[0];   // (B, T, E)
    const float* h0 = (const float*)d_in[1];   // (L, B, H)
    const float* c0 = (const float*)d_in[2];   // (L, B, H)
    const float* Wu = (const float*)d_in[3];   // (L, 2048, H)
    const float* bu = (const float*)d_in[4];   // (L, H)
    const float* Wf = (const float*)d_in[5];
    const float* bf = (const float*)d_in[6];
    const float* Wo = (const float*)d_in[7];
    const float* bo = (const float*)d_in[8];
    const float* Wc = (const float*)d_in[9];
    const float* bc = (const float*)d_in[10];

    float* out = (float*)d_out;
    float* outHidden = out;                                   // (B, T, H)
    float* outMem    = out + (size_t)BATCH * TIME * HDIM;     // (B, T, H)
    float* outHt     = out + (size_t)2 * BATCH * TIME * HDIM; // (B, 1, H)
    float* outCt     = outHt + (size_t)BATCH * HDIM;          // (B, 1, H)

    float *buf0, *buf1, *crun, *gpre, *wr, *xr, *h0r;
    cudaGetSymbolAddress((void**)&buf0, g_buf0);
    cudaGetSymbolAddress((void**)&buf1, g_buf1);
    cudaGetSymbolAddress((void**)&crun, g_crun);
    cudaGetSymbolAddress((void**)&gpre, g_pre);
    cudaGetSymbolAddress((void**)&wr,   g_wr);
    cudaGetSymbolAddress((void**)&xr,   g_xr);
    cudaGetSymbolAddress((void**)&h0r,  g_h0r);

    const size_t WSZ = (size_t)LAYERS * 2048 * HDIM;   // per gate
    float* Wu_r = wr;
    float* Wf_r = wr + WSZ;
    float* Wo_r = wr + 2 * WSZ;
    float* Wc_r = wr + 3 * WSZ;

    // Prep: round all MMA operands to tf32 grid once per launch.
    {
        const dim3 pblk(256), pgrid(1184);
        prep_round<<<pgrid, pblk>>>((const float4*)Wu, (float4*)Wu_r, WSZ / 4);
        prep_round<<<pgrid, pblk>>>((const float4*)Wf, (float4*)Wf_r, WSZ / 4);
        prep_round<<<pgrid, pblk>>>((const float4*)Wo, (float4*)Wo_r, WSZ / 4);
        prep_round<<<pgrid, pblk>>>((const float4*)Wc, (float4*)Wc_r, WSZ / 4);
        prep_round<<<pgrid, pblk>>>((const float4*)x,  (float4*)xr,
                                    (size_t)BATCH * TIME * EDIM / 4);
        prep_round<<<pgrid, pblk>>>((const float4*)h0, (float4*)h0r,
                                    (size_t)LAYERS * BATCH * HDIM / 4);
    }

    const int GSMEM = STAGES * STAGE_F * 4;   // 86016 B
    cudaFuncSetAttribute(lstm_pre,  cudaFuncAttributeMaxDynamicSharedMemorySize, GSMEM);
    cudaFuncSetAttribute(lstm_step, cudaFuncAttributeMaxDynamicSharedMemorySize, GSMEM);

    const dim3 blk(256);
    const dim3 gridPre(HDIM / 32, (BATCH * TIME) / BM);  // (32, 32) = 1024 blocks
    const dim3 gridStep(HDIM / 32, BATCH / BM);          // (32, 4)  = 128 blocks

    for (int l = 0; l < LAYERS; l++) {
        const size_t wOff = (size_t)l * 2048 * HDIM;
        const size_t bOff = (size_t)l * HDIM;
        const float* Wu_l = Wu_r + wOff;
        const float* Wf_l = Wf_r + wOff;
        const float* Wo_l = Wo_r + wOff;
        const float* Wc_l = Wc_r + wOff;

        const float* Aprev;
        int strideA;
        if (l == 0) { Aprev = xr; strideA = EDIM; }
        else { Aprev = ((l - 1) & 1) ? buf1 : buf0; strideA = HDIM; }
        float* cur = (l & 1) ? buf1 : buf0;   // rounded recurrence buffer (all layers)
        const bool last = (l == LAYERS - 1);

        lstm_pre<<<gridPre, blk, GSMEM>>>(Aprev, strideA,
                                          Wu_l, Wf_l, Wo_l, Wc_l, gpre);

        const float* Wu_h = Wu_l + (size_t)EDIM * HDIM;
        const float* Wf_h = Wf_l + (size_t)EDIM * HDIM;
        const float* Wo_h = Wo_l + (size_t)EDIM * HDIM;
        const float* Wc_h = Wc_l + (size_t)EDIM * HDIM;

        for (int t = 0; t < TIME; t++) {
            const float* hbase;
            int hstride;
            if (t == 0) { hbase = h0r + (size_t)l * BATCH * HDIM; hstride = HDIM; }
            else        { hbase = cur + (size_t)(t - 1) * HDIM;   hstride = TIME * HDIM; }
            const float* coldsrc = (t == 0) ? (c0 + (size_t)l * BATCH * HDIM) : crun;
            float* hrow   = cur + (size_t)t * HDIM;
            float* hexact = last ? (outHidden + (size_t)t * HDIM) : nullptr;
            float* crow   = last ? (outMem + (size_t)t * HDIM) : nullptr;
            float* oHt    = (last && t == TIME - 1) ? outHt : nullptr;
            float* oCt    = (last && t == TIME - 1) ? outCt : nullptr;

            lstm_step<<<gridStep, blk, GSMEM>>>(hbase, hstride,
                                                Wu_h, Wf_h, Wo_h, Wc_h,
                                                bu + bOff, bf + bOff, bo + bOff, bc + bOff,
                                                gpre, t, coldsrc, crun, hrow, hexact,
                                                crow, oHt, oCt);
        }
    }
}

// round 10
// speedup vs baseline: 1.6064x; 1.0003x over previous
#include <cuda_runtime.h>
#include <math.h>
#include <stdint.h>

// Problem constants
#define LAYERS 8
#define BATCH  256
#define TIME   8
#define EDIM   1024
#define HDIM   1024

#define BM     64
#define BK     32
#define KT     32      // 1024 / BK
#define STAGES 3

// Scratch buffers
__device__ float g_buf0[BATCH * TIME * HDIM];            // layer outputs, tf32-rounded (B,T,H)
__device__ float g_buf1[BATCH * TIME * HDIM];
__device__ float g_crun[BATCH * HDIM];                   // running cell state (exact fp32)
__device__ float g_pre[(size_t)BATCH * TIME * 4 * HDIM]; // x-part gate preacts (exact fp32)
// Pre-rounded MMA operands
__device__ float g_wr[(size_t)4 * LAYERS * 2048 * HDIM]; // [gate][l][k][j], 268 MB
__device__ float g_xr[BATCH * TIME * EDIM];              // rounded x
__device__ float g_h0r[LAYERS * BATCH * HDIM];           // rounded h0

__device__ __forceinline__ float f2tf32f(float f) {
    float r;
    asm("{ .reg .b32 t; cvt.rna.tf32.f32 t, %1; mov.b32 %0, t; }" : "=f"(r) : "f"(f));
    return r;
}

__device__ __forceinline__ void mma_tf32(float c[4],
                                         uint32_t a0, uint32_t a1, uint32_t a2, uint32_t a3,
                                         uint32_t b0, uint32_t b1) {
    asm volatile(
        "mma.sync.aligned.m16n8k8.row.col.f32.tf32.tf32.f32 "
        "{%0,%1,%2,%3}, {%4,%5,%6,%7}, {%8,%9}, {%0,%1,%2,%3};"
        : "+f"(c[0]), "+f"(c[1]), "+f"(c[2]), "+f"(c[3])
        : "r"(a0), "r"(a1), "r"(a2), "r"(a3), "r"(b0), "r"(b1));
}

__device__ __forceinline__ void cp16(float* dst, const float* src) {
    uint32_t d = (uint32_t)__cvta_generic_to_shared(dst);
    asm volatile("cp.async.cg.shared.global [%0], [%1], 16;" :: "r"(d), "l"(src));
}
__device__ __forceinline__ void cp_commit() {
    asm volatile("cp.async.commit_group;");
}
template <int N> __device__ __forceinline__ void cp_wait() {
    asm volatile("cp.async.wait_group %0;" :: "n"(N));
}

// ---------------------------------------------------------------------------
// Prep: elementwise round-to-nearest tf32 copy (float4 grid-stride).
// ---------------------------------------------------------------------------
__global__ __launch_bounds__(256)
void prep_round(const float4* __restrict__ src, float4* __restrict__ dst, size_t n4) {
    size_t i = (size_t)blockIdx.x * blockDim.x + threadIdx.x;
    const size_t stride = (size_t)gridDim.x * blockDim.x;
    for (; i < n4; i += stride) {
        float4 v = src[i];
        v.x = f2tf32f(v.x); v.y = f2tf32f(v.y);
        v.z = f2tf32f(v.z); v.w = f2tf32f(v.w);
        dst[i] = v;
    }
}

// -----------------------------------------------------------------------------
// GEMM mainloop: acc += A[r0:r0+64, 0:1024] @ [Wu|Wf|Wo|Wc][0:1024, j0:j0+32]
// All operands pre-rounded to tf32 grid -> raw bit loads, zero cvt in loop.
// A tile: 64x32 floats, XOR-swizzled (seg ^= row&7), stride 32 (conflict-free).
// B tile: [4*32][40] padded rows. Single __syncthreads per K-iteration.
// -----------------------------------------------------------------------------
#define BSTR    40
#define A_F     (64 * 32)
#define STAGE_F (A_F + 4 * 32 * BSTR)   // 2048 + 5120 = 7168 floats

__device__ __forceinline__ void gemm_main(
    float* smem,
    const float* __restrict__ Aptr, int strideA, int r0,
    const float* __restrict__ Wu, const float* __restrict__ Wf,
    const float* __restrict__ Wo, const float* __restrict__ Wc,
    int j0, float acc[2][4][4])
{
    const int tid  = threadIdx.x;
    const int lane = tid & 31;
    const int warp = tid >> 5;
    const int wy   = warp >> 2;       // row half
    const int wx   = warp & 3;        // gate
    const int g4   = lane >> 2;
    const int t4   = lane & 3;

    // A cp.async mapping: 64 rows x 8 segs(16B); 2 segs/thread
    const int aRow = tid >> 2;
    const int aSeg = tid & 3;
    const int aSw0 = ((aSeg)     ^ (aRow & 7)) * 4;
    const int aSw1 = ((aSeg + 4) ^ (aRow & 7)) * 4;
    const float* aSrc = Aptr + (size_t)(r0 + aRow) * strideA;

    // B cp.async mapping: 128 (gate,krow) rows x 8 segs; 4 segs/thread
    const int grow    = tid >> 1;            // 0..127 = gate*32 + krow
    const int gate    = grow >> 5;
    const int krow    = grow & 31;
    const int segBase = (tid & 1) * 4;
    const float* Wsel = (gate == 0) ? Wu : (gate == 1) ? Wf : (gate == 2) ? Wo : Wc;
    const float* wSrc = Wsel + (size_t)krow * HDIM + j0 + segBase * 4;

    auto issue = [&](int c) {
        float* sA = smem + (c % STAGES) * STAGE_F;
        float* sB = sA + A_F;
        const int k0 = c * BK;
        cp16(sA + aRow * 32 + aSw0, aSrc + k0 + aSeg * 4);
        cp16(sA + aRow * 32 + aSw1, aSrc + k0 + (aSeg + 4) * 4);
        const float* ws = wSrc + (size_t)k0 * HDIM;
        float* wd = sB + grow * BSTR + segBase * 4;
        #pragma unroll
        for (int s = 0; s < 4; s++) cp16(wd + s * 4, ws + s * 4);
        cp_commit();
    };

    auto compute = [&](int slot) {
        const float* sA = smem + slot * STAGE_F;
        const float* sB = sA + A_F + wx * (32 * BSTR);
        #pragma unroll
        for (int q = 0; q < 4; q++) {
            uint32_t a[2][4];
            #pragma unroll
            for (int mi = 0; mi < 2; mi++) {
                const float* pa = sA + (32 * wy + 16 * mi + g4) * 32 + t4;
                a[mi][0] = __float_as_uint(pa[((2 * q)     ^ g4) * 4]);
                a[mi][1] = __float_as_uint(pa[256 + ((2 * q)     ^ g4) * 4]);
                a[mi][2] = __float_as_uint(pa[((2 * q + 1) ^ g4) * 4]);
                a[mi][3] = __float_as_uint(pa[256 + ((2 * q + 1) ^ g4) * 4]);
            }
            const int kr = 8 * q + t4;
            #pragma unroll
            for (int ni = 0; ni < 4; ni++) {
                const int col = 8 * ni + g4;
                const uint32_t b0 = __float_as_uint(sB[kr * BSTR + col]);
                const uint32_t b1 = __float_as_uint(sB[(kr + 4) * BSTR + col]);
                mma_tf32(acc[0][ni], a[0][0], a[0][1], a[0][2], a[0][3], b0, b1);
                mma_tf32(acc[1][ni], a[1][0], a[1][1], a[1][2], a[1][3], b0, b1);
            }
        }
    };

    issue(0);
    issue(1);
    #pragma unroll 1
    for (int c = 0; c < KT; c++) {
        cp_wait<STAGES - 2>();       // stage c's groups complete (this thread)
        __syncthreads();             // publish arrivals + protect slot reuse
        if (c + 2 < KT) issue(c + 2); else cp_commit();
        compute(c % STAGES);
    }
}

// ---------------------------------------------------------------------------
// Pre-kernel: x-part GEMM for a whole layer (rows r = b*T + t).
// ---------------------------------------------------------------------------
__global__ __launch_bounds__(256)
void lstm_pre(const float* __restrict__ A, int strideA,
              const float* __restrict__ Wu, const float* __restrict__ Wf,
              const float* __restrict__ Wo, const float* __restrict__ Wc,
              float* __restrict__ Gpre)
{
    extern __shared__ float smem[];
    const int j0 = blockIdx.x * 32;
    const int r0 = blockIdx.y * BM;

    float acc[2][4][4];
    #pragma unroll
    for (int mi = 0; mi < 2; mi++)
        #pragma unroll
        for (int ni = 0; ni < 4; ni++)
            #pragma unroll
            for (int r = 0; r < 4; r++) acc[mi][ni][r] = 0.0f;

    gemm_main(smem, A, strideA, r0, Wu, Wf, Wo, Wc, j0, acc);

    const int lane = threadIdx.x & 31;
    const int warp = threadIdx.x >> 5;
    const int wy = warp >> 2, wx = warp & 3;
    const int g4 = lane >> 2, t4 = lane & 3;

    #pragma unroll
    for (int mi = 0; mi < 2; mi++) {
        #pragma unroll
        for (int ni = 0; ni < 4; ni++) {
            const int row = r0 + 32 * wy + 16 * mi + g4;
            const int col = j0 + 8 * ni + 2 * t4;
            *(float2*)(Gpre + ((size_t)row * 4 + wx) * HDIM + col) =
                make_float2(acc[mi][ni][0], acc[mi][ni][1]);
            *(float2*)(Gpre + ((size_t)(row + 8) * 4 + wx) * HDIM + col) =
                make_float2(acc[mi][ni][2], acc[mi][ni][3]);
        }
    }
}

// ---------------------------------------------------------------------------
// Step kernel: h-recurrent GEMM (K=1024, 64x128 tile) + fused LSTM cell update.
// Writes rounded h into the recurrence buffer; exact values into outputs.
// ---------------------------------------------------------------------------
#define GS_STRIDE 130

__global__ __launch_bounds__(256)
void lstm_step(const float* __restrict__ hbase, int hstride,
               const float* __restrict__ Wu, const float* __restrict__ Wf,
               const float* __restrict__ Wo, const float* __restrict__ Wc,
               const float* __restrict__ bu, const float* __restrict__ bf,
               const float* __restrict__ bo, const float* __restrict__ bc,
               const float* __restrict__ Gpre, int t,
               const float* __restrict__ c_old_src,
               float* __restrict__ c_run,
               float* __restrict__ hrow,              // rounded h, buf, stride T*H
               float* __restrict__ hexact,            // outHidden row or null
               float* __restrict__ crow,              // outMem row or null
               float* __restrict__ outHt, float* __restrict__ outCt)
{
    extern __shared__ float smem[];
    const int j0 = blockIdx.x * 32;
    const int b0 = blockIdx.y * BM;

    float acc[2][4][4];
    #pragma unroll
    for (int mi = 0; mi < 2; mi++)
        #pragma unroll
        for (int ni = 0; ni < 4; ni++)
            #pragma unroll
            for (int r = 0; r < 4; r++) acc[mi][ni][r] = 0.0f;

    gemm_main(smem, hbase, hstride, b0, Wu, Wf, Wo, Wc, j0, acc);

    cp_wait<0>();
    __syncthreads();

    // Gate exchange through smem: 64 rows x (4 gates x 32 cols)
    float* gs = smem;
    {
        const int lane = threadIdx.x & 31;
        const int warp = threadIdx.x >> 5;
        const int wy = warp >> 2, wx = warp & 3;
        const int g4 = lane >> 2, t4 = lane & 3;
        #pragma unroll
        for (int mi = 0; mi < 2; mi++) {
            #pragma unroll
            for (int ni = 0; ni < 4; ni++) {
                const int row = 32 * wy + 16 * mi + g4;
                const int col = wx * 32 + 8 * ni + 2 * t4;
                *(float2*)(gs + row * GS_STRIDE + col) =
                    make_float2(acc[mi][ni][0], acc[mi][ni][1]);
                *(float2*)(gs + (row + 8) * GS_STRIDE + col) =
                    make_float2(acc[mi][ni][2], acc[mi][ni][3]);
            }
        }
    }
    __syncthreads();

    const int jj = threadIdx.x & 31;
    const int r0 = threadIdx.x >> 5;
    const int j  = j0 + jj;
    const float b_u = bu[j], b_f = bf[j], b_o = bo[j], b_c = bc[j];

    #pragma unroll
    for (int i = 0; i < 8; i++) {
        const int row = r0 + 8 * i;
        const int b   = b0 + row;
        const size_t gbase = ((size_t)(b * TIME + t) * 4) * HDIM + j;
        const float su = gs[row * GS_STRIDE +      jj] + Gpre[gbase]            + b_u;
        const float sf = gs[row * GS_STRIDE + 32 + jj] + Gpre[gbase +     HDIM] + b_f;
        const float so = gs[row * GS_STRIDE + 64 + jj] + Gpre[gbase + 2 * HDIM] + b_o;
        const float sc = gs[row * GS_STRIDE + 96 + jj] + Gpre[gbase + 3 * HDIM] + b_c;
        const float u  = 1.0f / (1.0f + expf(-su));
        const float f  = 1.0f / (1.0f + expf(-sf));
        const float o  = 1.0f / (1.0f + expf(-so));
        const float ct = tanhf(sc);
        const size_t idx = (size_t)b * HDIM + j;
        const float c_new = f * c_old_src[idx] + u * ct;
        const float h_new = o * tanhf(c_new);
        c_run[idx] = c_new;
        const size_t ridx = (size_t)b * (TIME * HDIM) + j;
        hrow[ridx] = f2tf32f(h_new);          // rounded: GEMM input only
        if (hexact) { hexact[ridx] = h_new; crow[ridx] = c_new; }
        if (outHt) { outHt[idx] = h_new; outCt[idx] = c_new; }
    }
}

extern "C" void kernel_launch(void* const* d_in, const int* in_sizes, int n_in,
                              void* d_out, int out_size) {
    const float* x  = (const float*)d_in[0];   // (B, T, E)
    const float* h0 = (const float*)d_in[1];   // (L, B, H)
    const float* c0 = (const float*)d_in[2];   // (L, B, H)
    const float* Wu = (const float*)d_in[3];   // (L, 2048, H)
    const float* bu = (const float*)d_in[4];   // (L, H)
    const float* Wf = (const float*)d_in[5];
    const float* bf = (const float*)d_in[6];
    const float* Wo = (const float*)d_in[7];
    const float* bo = (const float*)d_in[8];
    const float* Wc = (const float*)d_in[9];
    const float* bc = (const float*)d_in[10];

    float* out = (float*)d_out;
    float* outHidden = out;                                   // (B, T, H)
    float* outMem    = out + (size_t)BATCH * TIME * HDIM;     // (B, T, H)
    float* outHt     = out + (size_t)2 * BATCH * TIME * HDIM; // (B, 1, H)
    float* outCt     = outHt + (size_t)BATCH * HDIM;          // (B, 1, H)

    float *buf0, *buf1, *crun, *gpre, *wr, *xr, *h0r;
    cudaGetSymbolAddress((void**)&buf0, g_buf0);
    cudaGetSymbolAddress((void**)&buf1, g_buf1);
    cudaGetSymbolAddress((void**)&crun, g_crun);
    cudaGetSymbolAddress((void**)&gpre, g_pre);
    cudaGetSymbolAddress((void**)&wr,   g_wr);
    cudaGetSymbolAddress((void**)&xr,   g_xr);
    cudaGetSymbolAddress((void**)&h0r,  g_h0r);

    const size_t WSZ = (size_t)LAYERS * 2048 * HDIM;   // per gate
    float* Wu_r = wr;
    float* Wf_r = wr + WSZ;
    float* Wo_r = wr + 2 * WSZ;
    float* Wc_r = wr + 3 * WSZ;

    // Prep: round all MMA operands to tf32 grid once per launch.
    {
        const dim3 pblk(256), pgrid(1184);
        prep_round<<<pgrid, pblk>>>((const float4*)Wu, (float4*)Wu_r, WSZ / 4);
        prep_round<<<pgrid, pblk>>>((const float4*)Wf, (float4*)Wf_r, WSZ / 4);
        prep_round<<<pgrid, pblk>>>((const float4*)Wo, (float4*)Wo_r, WSZ / 4);
        prep_round<<<pgrid, pblk>>>((const float4*)Wc, (float4*)Wc_r, WSZ / 4);
        prep_round<<<pgrid, pblk>>>((const float4*)x,  (float4*)xr,
                                    (size_t)BATCH * TIME * EDIM / 4);
        prep_round<<<pgrid, pblk>>>((const float4*)h0, (float4*)h0r,
                                    (size_t)LAYERS * BATCH * HDIM / 4);
    }

    const int GSMEM = STAGES * STAGE_F * 4;   // 86016 B
    cudaFuncSetAttribute(lstm_pre,  cudaFuncAttributeMaxDynamicSharedMemorySize, GSMEM);
    cudaFuncSetAttribute(lstm_step, cudaFuncAttributeMaxDynamicSharedMemorySize, GSMEM);

    const dim3 blk(256);
    const dim3 gridPre(HDIM / 32, (BATCH * TIME) / BM);  // (32, 32) = 1024 blocks
    const dim3 gridStep(HDIM / 32, BATCH / BM);          // (32, 4)  = 128 blocks

    for (int l = 0; l < LAYERS; l++) {
        const size_t wOff = (size_t)l * 2048 * HDIM;
        const size_t bOff = (size_t)l * HDIM;
        const float* Wu_l = Wu_r + wOff;
        const float* Wf_l = Wf_r + wOff;
        const float* Wo_l = Wo_r + wOff;
        const float* Wc_l = Wc_r + wOff;

        const float* Aprev;
        int strideA;
        if (l == 0) { Aprev = xr; strideA = EDIM; }
        else { Aprev = ((l - 1) & 1) ? buf1 : buf0; strideA = HDIM; }
        float* cur = (l & 1) ? buf1 : buf0;   // rounded recurrence buffer (all layers)
        const bool last = (l == LAYERS - 1);

        lstm_pre<<<gridPre, blk, GSMEM>>>(Aprev, strideA,
                                          Wu_l, Wf_l, Wo_l, Wc_l, gpre);

        const float* Wu_h = Wu_l + (size_t)EDIM * HDIM;
        const float* Wf_h = Wf_l + (size_t)EDIM * HDIM;
        const float* Wo_h = Wo_l + (size_t)EDIM * HDIM;
        const float* Wc_h = Wc_l + (size_t)EDIM * HDIM;

        for (int t = 0; t < TIME; t++) {
            const float* hbase;
            int hstride;
            if (t == 0) { hbase = h0r + (size_t)l * BATCH * HDIM; hstride = HDIM; }
            else        { hbase = cur + (size_t)(t - 1) * HDIM;   hstride = TIME * HDIM; }
            const float* coldsrc = (t == 0) ? (c0 + (size_t)l * BATCH * HDIM) : crun;
            float* hrow   = cur + (size_t)t * HDIM;
            float* hexact = last ? (outHidden + (size_t)t * HDIM) : nullptr;
            float* crow   = last ? (outMem + (size_t)t * HDIM) : nullptr;
            float* oHt    = (last && t == TIME - 1) ? outHt : nullptr;
            float* oCt    = (last && t == TIME - 1) ? outCt : nullptr;

            lstm_step<<<gridStep, blk, GSMEM>>>(hbase, hstride,
                                                Wu_h, Wf_h, Wo_h, Wc_h,
                                                bu + bOff, bf + bOff, bo + bOff, bc + bOff,
                                                gpre, t, coldsrc, crun, hrow, hexact,
                                                crow, oHt, oCt);
        }
    }
}

// round 11
// speedup vs baseline: 1.8094x; 1.1264x over previous
#include <cuda_runtime.h>
#include <math.h>
#include <stdint.h>

// Problem constants
#define LAYERS 8
#define BATCH  256
#define TIME   8
#define EDIM   1024
#define HDIM   1024
#define KDIM   2048

#define BM     64
#define BK     32
#define KT2    64      // 2048 / BK
#define STAGES 3

// Scratch buffers
__device__ float g_hwA[LAYERS * BATCH * HDIM];           // wave ping-pong h (tf32-rounded)
__device__ float g_hwB[LAYERS * BATCH * HDIM];
__device__ float g_crun[LAYERS * BATCH * HDIM];          // per-layer running cell state (exact)
// Pre-rounded MMA operands
__device__ float g_wr[(size_t)4 * LAYERS * KDIM * HDIM]; // [gate][l][k][j], 268 MB
__device__ float g_xr[BATCH * TIME * EDIM];              // rounded x
__device__ float g_h0r[LAYERS * BATCH * HDIM];           // rounded h0

__device__ __forceinline__ float f2tf32f(float f) {
    float r;
    asm("{ .reg .b32 t; cvt.rna.tf32.f32 t, %1; mov.b32 %0, t; }" : "=f"(r) : "f"(f));
    return r;
}

__device__ __forceinline__ void mma_tf32(float c[4],
                                         uint32_t a0, uint32_t a1, uint32_t a2, uint32_t a3,
                                         uint32_t b0, uint32_t b1) {
    asm volatile(
        "mma.sync.aligned.m16n8k8.row.col.f32.tf32.tf32.f32 "
        "{%0,%1,%2,%3}, {%4,%5,%6,%7}, {%8,%9}, {%0,%1,%2,%3};"
        : "+f"(c[0]), "+f"(c[1]), "+f"(c[2]), "+f"(c[3])
        : "r"(a0), "r"(a1), "r"(a2), "r"(a3), "r"(b0), "r"(b1));
}

__device__ __forceinline__ void cp16(float* dst, const float* src) {
    uint32_t d = (uint32_t)__cvta_generic_to_shared(dst);
    asm volatile("cp.async.cg.shared.global [%0], [%1], 16;" :: "r"(d), "l"(src));
}
__device__ __forceinline__ void cp_commit() {
    asm volatile("cp.async.commit_group;");
}
template <int N> __device__ __forceinline__ void cp_wait() {
    asm volatile("cp.async.wait_group %0;" :: "n"(N));
}

// ---------------------------------------------------------------------------
// Prep: elementwise round-to-nearest tf32 copy (float4 grid-stride).
// ---------------------------------------------------------------------------
__global__ __launch_bounds__(256)
void prep_round(const float4* __restrict__ src, float4* __restrict__ dst, size_t n4) {
    size_t i = (size_t)blockIdx.x * blockDim.x + threadIdx.x;
    const size_t stride = (size_t)gridDim.x * blockDim.x;
    for (; i < n4; i += stride) {
        float4 v = src[i];
        v.x = f2tf32f(v.x); v.y = f2tf32f(v.y);
        v.z = f2tf32f(v.z); v.w = f2tf32f(v.w);
        dst[i] = v;
    }
}

// -----------------------------------------------------------------------------
// GEMM mainloop, K = 2048 = [input 1024 | h 1024]:
//   acc += [inA | hB][r0:r0+64, :] @ [Wu|Wf|Wo|Wc][0:2048, j0:j0+32]
// All operands pre-rounded to tf32 grid -> raw bit loads, zero cvt in loop.
// A tile: 64x32 floats, XOR-swizzled; B tile: [4*32][40]. Single sync per iter.
// -----------------------------------------------------------------------------
#define BSTR    40
#define A_F     (64 * 32)
#define STAGE_F (A_F + 4 * 32 * BSTR)   // 7168 floats

__device__ __forceinline__ void gemm_k2048(
    float* smem,
    const float* __restrict__ inA, int strideIn,      // k in [0,1024)
    const float* __restrict__ hB,                     // k in [1024,2048), stride HDIM
    int r0,
    const float* __restrict__ Wu, const float* __restrict__ Wf,
    const float* __restrict__ Wo, const float* __restrict__ Wc,
    int j0, float acc[2][4][4])
{
    const int tid  = threadIdx.x;
    const int lane = tid & 31;
    const int warp = tid >> 5;
    const int wy   = warp >> 2;
    const int wx   = warp & 3;
    const int g4   = lane >> 2;
    const int t4   = lane & 3;

    // A cp.async mapping: 64 rows x 8 segs(16B); 2 segs/thread
    const int aRow = tid >> 2;
    const int aSeg = tid & 3;
    const int aSw0 = ((aSeg)     ^ (aRow & 7)) * 4;
    const int aSw1 = ((aSeg + 4) ^ (aRow & 7)) * 4;
    const float* aSrcIn = inA + (size_t)(r0 + aRow) * strideIn;
    const float* aSrcH  = hB  + (size_t)(r0 + aRow) * HDIM;

    // B cp.async mapping: 128 (gate,krow) rows x 8 segs; 4 segs/thread
    const int grow    = tid >> 1;
    const int gate    = grow >> 5;
    const int krow    = grow & 31;
    const int segBase = (tid & 1) * 4;
    const float* Wsel = (gate == 0) ? Wu : (gate == 1) ? Wf : (gate == 2) ? Wo : Wc;
    const float* wSrc = Wsel + (size_t)krow * HDIM + j0 + segBase * 4;

    auto issue = [&](int c) {
        float* sA = smem + (c % STAGES) * STAGE_F;
        float* sB = sA + A_F;
        const int k0 = c * BK;
        const float* s = (k0 < EDIM) ? (aSrcIn + k0) : (aSrcH + (k0 - EDIM));
        cp16(sA + aRow * 32 + aSw0, s + aSeg * 4);
        cp16(sA + aRow * 32 + aSw1, s + (aSeg + 4) * 4);
        const float* ws = wSrc + (size_t)k0 * HDIM;
        float* wd = sB + grow * BSTR + segBase * 4;
        #pragma unroll
        for (int q = 0; q < 4; q++) cp16(wd + q * 4, ws + q * 4);
        cp_commit();
    };

    auto compute = [&](int slot) {
        const float* sA = smem + slot * STAGE_F;
        const float* sB = sA + A_F + wx * (32 * BSTR);
        #pragma unroll
        for (int q = 0; q < 4; q++) {
            uint32_t a[2][4];
            #pragma unroll
            for (int mi = 0; mi < 2; mi++) {
                const float* pa = sA + (32 * wy + 16 * mi + g4) * 32 + t4;
                a[mi][0] = __float_as_uint(pa[((2 * q)     ^ g4) * 4]);
                a[mi][1] = __float_as_uint(pa[256 + ((2 * q)     ^ g4) * 4]);
                a[mi][2] = __float_as_uint(pa[((2 * q + 1) ^ g4) * 4]);
                a[mi][3] = __float_as_uint(pa[256 + ((2 * q + 1) ^ g4) * 4]);
            }
            const int kr = 8 * q + t4;
            #pragma unroll
            for (int ni = 0; ni < 4; ni++) {
                const int col = 8 * ni + g4;
                const uint32_t b0 = __float_as_uint(sB[kr * BSTR + col]);
                const uint32_t b1 = __float_as_uint(sB[(kr + 4) * BSTR + col]);
                mma_tf32(acc[0][ni], a[0][0], a[0][1], a[0][2], a[0][3], b0, b1);
                mma_tf32(acc[1][ni], a[1][0], a[1][1], a[1][2], a[1][3], b0, b1);
            }
        }
    };

    issue(0);
    issue(1);
    #pragma unroll 1
    for (int c = 0; c < KT2; c++) {
        cp_wait<STAGES - 2>();
        __syncthreads();
        if (c + 2 < KT2) issue(c + 2); else cp_commit();
        compute(c % STAGES);
    }
}

// ---------------------------------------------------------------------------
// Wave kernel: all cells (l, t) with l + t == w. grid = (32 jblk, 4 bblk, cells).
// Each cell: full K=2048 gate GEMM + fused LSTM cell update.
// ---------------------------------------------------------------------------
#define GS_STRIDE 130

__global__ __launch_bounds__(256)
void lstm_wave(int w, int l_lo,
               const float* __restrict__ hwPrev, float* __restrict__ hwCur,
               const float* __restrict__ xr, const float* __restrict__ h0r,
               const float* __restrict__ c0,
               const float* __restrict__ WuB, const float* __restrict__ WfB,
               const float* __restrict__ WoB, const float* __restrict__ WcB,
               const float* __restrict__ bu, const float* __restrict__ bf,
               const float* __restrict__ bo, const float* __restrict__ bc,
               float* __restrict__ crun,
               float* __restrict__ outH, float* __restrict__ outC,
               float* __restrict__ outHt, float* __restrict__ outCt)
{
    extern __shared__ float smem[];
    const int l  = l_lo + blockIdx.z;
    const int t  = w - l;
    const int j0 = blockIdx.x * 32;
    const int b0 = blockIdx.y * BM;

    // Per-cell operand pointers
    const float* inA;
    int strideIn;
    if (l == 0) { inA = xr + (size_t)t * EDIM; strideIn = TIME * EDIM; }
    else        { inA = hwPrev + (size_t)(l - 1) * BATCH * HDIM; strideIn = HDIM; }
    const float* hB = (t == 0) ? (h0r + (size_t)l * BATCH * HDIM)
                               : (hwPrev + (size_t)l * BATCH * HDIM);
    const size_t wOff = (size_t)l * KDIM * HDIM;

    float acc[2][4][4];
    #pragma unroll
    for (int mi = 0; mi < 2; mi++)
        #pragma unroll
        for (int ni = 0; ni < 4; ni++)
            #pragma unroll
            for (int r = 0; r < 4; r++) acc[mi][ni][r] = 0.0f;

    gemm_k2048(smem, inA, strideIn, hB, b0,
               WuB + wOff, WfB + wOff, WoB + wOff, WcB + wOff, j0, acc);

    cp_wait<0>();
    __syncthreads();

    // Gate exchange through smem: 64 rows x (4 gates x 32 cols)
    float* gs = smem;
    {
        const int lane = threadIdx.x & 31;
        const int warp = threadIdx.x >> 5;
        const int wy = warp >> 2, wx = warp & 3;
        const int g4 = lane >> 2, t4 = lane & 3;
        #pragma unroll
        for (int mi = 0; mi < 2; mi++) {
            #pragma unroll
            for (int ni = 0; ni < 4; ni++) {
                const int row = 32 * wy + 16 * mi + g4;
                const int col = wx * 32 + 8 * ni + 2 * t4;
                *(float2*)(gs + row * GS_STRIDE + col) =
                    make_float2(acc[mi][ni][0], acc[mi][ni][1]);
                *(float2*)(gs + (row + 8) * GS_STRIDE + col) =
                    make_float2(acc[mi][ni][2], acc[mi][ni][3]);
            }
        }
    }
    __syncthreads();

    const int jj = threadIdx.x & 31;
    const int r0 = threadIdx.x >> 5;
    const int j  = j0 + jj;
    const float b_u = bu[l * HDIM + j], b_f = bf[l * HDIM + j];
    const float b_o = bo[l * HDIM + j], b_c = bc[l * HDIM + j];

    float* cl = crun + (size_t)l * BATCH * HDIM;
    const float* colds = (t == 0) ? (c0 + (size_t)l * BATCH * HDIM) : cl;
    float* hcur = hwCur + (size_t)l * BATCH * HDIM;
    const bool last = (l == LAYERS - 1);

    #pragma unroll
    for (int i = 0; i < 8; i++) {
        const int row = r0 + 8 * i;
        const int b   = b0 + row;
        const float su = gs[row * GS_STRIDE +      jj] + b_u;
        const float sf = gs[row * GS_STRIDE + 32 + jj] + b_f;
        const float so = gs[row * GS_STRIDE + 64 + jj] + b_o;
        const float sc = gs[row * GS_STRIDE + 96 + jj] + b_c;
        const float u  = 1.0f / (1.0f + expf(-su));
        const float f  = 1.0f / (1.0f + expf(-sf));
        const float o  = 1.0f / (1.0f + expf(-so));
        const float ct = tanhf(sc);
        const size_t idx = (size_t)b * HDIM + j;
        const float c_new = f * colds[idx] + u * ct;
        const float h_new = o * tanhf(c_new);
        cl[idx]   = c_new;
        hcur[idx] = f2tf32f(h_new);          // rounded: GEMM input for next wave
        if (last) {
            const size_t oidx = ((size_t)b * TIME + t) * HDIM + j;
            outH[oidx] = h_new;
            outC[oidx] = c_new;
            if (t == TIME - 1) { outHt[idx] = h_new; outCt[idx] = c_new; }
        }
    }
}

extern "C" void kernel_launch(void* const* d_in, const int* in_sizes, int n_in,
                              void* d_out, int out_size) {
    const float* x  = (const float*)d_in[0];   // (B, T, E)
    const float* h0 = (const float*)d_in[1];   // (L, B, H)
    const float* c0 = (const float*)d_in[2];   // (L, B, H)
    const float* Wu = (const float*)d_in[3];   // (L, 2048, H)
    const float* bu = (const float*)d_in[4];   // (L, H)
    const float* Wf = (const float*)d_in[5];
    const float* bf = (const float*)d_in[6];
    const float* Wo = (const float*)d_in[7];
    const float* bo = (const float*)d_in[8];
    const float* Wc = (const float*)d_in[9];
    const float* bc = (const float*)d_in[10];

    float* out = (float*)d_out;
    float* outHidden = out;                                   // (B, T, H)
    float* outMem    = out + (size_t)BATCH * TIME * HDIM;     // (B, T, H)
    float* outHt     = out + (size_t)2 * BATCH * TIME * HDIM; // (B, 1, H)
    float* outCt     = outHt + (size_t)BATCH * HDIM;          // (B, 1, H)

    float *hwA, *hwB, *crun, *wr, *xr, *h0r;
    cudaGetSymbolAddress((void**)&hwA,  g_hwA);
    cudaGetSymbolAddress((void**)&hwB,  g_hwB);
    cudaGetSymbolAddress((void**)&crun, g_crun);
    cudaGetSymbolAddress((void**)&wr,   g_wr);
    cudaGetSymbolAddress((void**)&xr,   g_xr);
    cudaGetSymbolAddress((void**)&h0r,  g_h0r);

    const size_t WSZ = (size_t)LAYERS * KDIM * HDIM;   // per gate
    float* Wu_r = wr;
    float* Wf_r = wr + WSZ;
    float* Wo_r = wr + 2 * WSZ;
    float* Wc_r = wr + 3 * WSZ;

    // Prep: round all MMA operands to tf32 grid once per launch.
    {
        const dim3 pblk(256), pgrid(1184);
        prep_round<<<pgrid, pblk>>>((const float4*)Wu, (float4*)Wu_r, WSZ / 4);
        prep_round<<<pgrid, pblk>>>((const float4*)Wf, (float4*)Wf_r, WSZ / 4);
        prep_round<<<pgrid, pblk>>>((const float4*)Wo, (float4*)Wo_r, WSZ / 4);
        prep_round<<<pgrid, pblk>>>((const float4*)Wc, (float4*)Wc_r, WSZ / 4);
        prep_round<<<pgrid, pblk>>>((const float4*)x,  (float4*)xr,
                                    (size_t)BATCH * TIME * EDIM / 4);
        prep_round<<<pgrid, pblk>>>((const float4*)h0, (float4*)h0r,
                                    (size_t)LAYERS * BATCH * HDIM / 4);
    }

    const int GSMEM = STAGES * STAGE_F * 4;   // 86016 B
    cudaFuncSetAttribute(lstm_wave, cudaFuncAttributeMaxDynamicSharedMemorySize, GSMEM);

    // Wavefront: wave w runs all cells (l, t) with l + t == w.
    for (int w = 0; w < LAYERS + TIME - 1; w++) {
        const int l_lo  = (w - (TIME - 1) > 0) ? (w - (TIME - 1)) : 0;
        const int l_hi  = (w < LAYERS - 1) ? w : (LAYERS - 1);
        const int cells = l_hi - l_lo + 1;
        const float* hwPrev = (w & 1) ? hwA : hwB;   // written at wave w-1
        float*       hwCur  = (w & 1) ? hwB : hwA;

        const dim3 grid(HDIM / 32, BATCH / BM, cells);   // (32, 4, cells)
        lstm_wave<<<grid, 256, GSMEM>>>(w, l_lo, hwPrev, hwCur,
                                        xr, h0r, c0,
                                        Wu_r, Wf_r, Wo_r, Wc_r,
                                        bu, bf, bo, bc,
                                        crun,
                                        outHidden, outMem, outHt, outCt);
    }
}

// round 12
// speedup vs baseline: 1.8540x; 1.0246x over previous
#include <cuda_runtime.h>
#include <math.h>
#include <stdint.h>

// Problem constants
#define LAYERS 8
#define BATCH  256
#define TIME   8
#define EDIM   1024
#define HDIM   1024
#define KDIM   2048

#define BM     64
#define BK     32
#define KT2    64      // 2048 / BK
#define STAGES 3

// Interleaved-pair layout:
//   k-groups of 8 are stored as pairs (k, k+4): in-group float position
//   pos(k) = 2*(k&3) + ((k>>2)&1). A thread's mma fragment pair becomes one
//   aligned float2 (LDS.64), halving shared-load instruction count.

// Scratch buffers
__device__ float g_hwA[LAYERS * BATCH * HDIM];           // wave ping-pong h (rounded+permuted)
__device__ float g_hwB[LAYERS * BATCH * HDIM];
__device__ float g_crun[LAYERS * BATCH * HDIM];          // per-layer running cell state (exact)
// Pre-rounded+packed MMA operands
__device__ float g_w2[(size_t)4 * LAYERS * KDIM * HDIM]; // packed weights, 268 MB
__device__ float g_xr[BATCH * TIME * EDIM];              // rounded+permuted x
__device__ float g_h0r[LAYERS * BATCH * HDIM];           // rounded+permuted h0

__device__ __forceinline__ float f2tf32f(float f) {
    float r;
    asm("{ .reg .b32 t; cvt.rna.tf32.f32 t, %1; mov.b32 %0, t; }" : "=f"(r) : "f"(f));
    return r;
}

__device__ __forceinline__ void mma_tf32(float c[4],
                                         uint32_t a0, uint32_t a1, uint32_t a2, uint32_t a3,
                                         uint32_t b0, uint32_t b1) {
    asm volatile(
        "mma.sync.aligned.m16n8k8.row.col.f32.tf32.tf32.f32 "
        "{%0,%1,%2,%3}, {%4,%5,%6,%7}, {%8,%9}, {%0,%1,%2,%3};"
        : "+f"(c[0]), "+f"(c[1]), "+f"(c[2]), "+f"(c[3])
        : "r"(a0), "r"(a1), "r"(a2), "r"(a3), "r"(b0), "r"(b1));
}

__device__ __forceinline__ void cp16(float* dst, const float* src) {
    uint32_t d = (uint32_t)__cvta_generic_to_shared(dst);
    asm volatile("cp.async.cg.shared.global [%0], [%1], 16;" :: "r"(d), "l"(src));
}
__device__ __forceinline__ void cp_commit() {
    asm volatile("cp.async.commit_group;");
}
template <int N> __device__ __forceinline__ void cp_wait() {
    asm volatile("cp.async.wait_group %0;" :: "n"(N));
}

// ---------------------------------------------------------------------------
// Prep kernels
// ---------------------------------------------------------------------------
// Activations: tf32-round + in-group-of-8 pair interleave.
__global__ __launch_bounds__(256)
void prep_act(const float4* __restrict__ src, float4* __restrict__ dst, size_t n8) {
    size_t i = (size_t)blockIdx.x * blockDim.x + threadIdx.x;
    const size_t stride = (size_t)gridDim.x * blockDim.x;
    for (; i < n8; i += stride) {
        float4 a = src[2 * i];
        float4 b = src[2 * i + 1];
        float4 o0 = make_float4(f2tf32f(a.x), f2tf32f(b.x), f2tf32f(a.y), f2tf32f(b.y));
        float4 o1 = make_float4(f2tf32f(a.z), f2tf32f(b.z), f2tf32f(a.w), f2tf32f(b.w));
        dst[2 * i]     = o0;
        dst[2 * i + 1] = o1;
    }
}

// Weights: W[l][k][j] -> W2[l][kp][j] of float2 (W[k_lo][j], W[k_lo+4][j]),
// kp = (k_lo>>3)*4 + (k_lo&3), with tf32 rounding. One gate per launch.
__global__ __launch_bounds__(256)
void prep_w(const float* __restrict__ W, float* __restrict__ W2, size_t njobs) {
    size_t i = (size_t)blockIdx.x * blockDim.x + threadIdx.x;
    const size_t stride = (size_t)gridDim.x * blockDim.x;
    for (; i < njobs; i += stride) {
        const int j4 = (int)(i & 255) * 4;
        const int kp = (int)(i >> 8) & 1023;
        const int l  = (int)(i >> 18);
        const int k_lo = (kp >> 2) * 8 + (kp & 3);
        const float* src = W + ((size_t)l * KDIM + k_lo) * HDIM + j4;
        float4 lo = *(const float4*)src;
        float4 hi = *(const float4*)(src + 4 * HDIM);
        float* d = W2 + ((size_t)l * 1024 + kp) * 2048 + (size_t)j4 * 2;
        *(float4*)d       = make_float4(f2tf32f(lo.x), f2tf32f(hi.x),
                                        f2tf32f(lo.y), f2tf32f(hi.y));
        *(float4*)(d + 4) = make_float4(f2tf32f(lo.z), f2tf32f(hi.z),
                                        f2tf32f(lo.w), f2tf32f(hi.w));
    }
}

// -----------------------------------------------------------------------------
// GEMM mainloop, K = 2048 = [input 1024 | h 1024], float2-fragment loads.
// A tile: 64 rows x 32 floats (pair-interleaved), row stride 40 floats.
// B tile: 4 gates x 16 pair-rows x 32 float2, pair-row stride 72 floats.
// -----------------------------------------------------------------------------
#define A_STR   40
#define B_STR   72
#define A_F     (64 * A_STR)               // 2560 floats
#define B_GATE  (16 * B_STR)               // 1152 floats
#define STAGE_F (A_F + 4 * B_GATE)         // 7168 floats

__device__ __forceinline__ void gemm_k2048(
    float* smem,
    const float* __restrict__ inA, int strideIn,      // k in [0,1024), packed rows
    const float* __restrict__ hB,                     // k in [1024,2048), stride HDIM
    int r0,
    const float* __restrict__ W2u, const float* __restrict__ W2f,
    const float* __restrict__ W2o, const float* __restrict__ W2c, // per-layer packed
    int j0, float acc[2][4][4])
{
    const int tid  = threadIdx.x;
    const int lane = tid & 31;
    const int warp = tid >> 5;
    const int wy   = warp >> 2;
    const int wx   = warp & 3;
    const int g4   = lane >> 2;
    const int t4   = lane & 3;

    // A cp.async mapping: 64 rows x 8 segs(16B); 2 segs/thread
    const int aRow = tid >> 2;
    const int aSeg = tid & 3;
    const float* aSrcIn = inA + (size_t)(r0 + aRow) * strideIn;
    const float* aSrcH  = hB  + (size_t)(r0 + aRow) * HDIM;
    float* const aDst0 = smem + aRow * A_STR + aSeg * 4;

    // B cp.async mapping: 64 (gate,prow) x 16 segs(16B); 4 segs/thread
    const int prow_g = tid >> 2;             // 0..63 = gate*16 + p
    const int gateB  = prow_g >> 4;
    const int pB     = prow_g & 15;
    const int segB   = (tid & 3) * 4;        // first of 4 consecutive segs
    const float* W2sel = (gateB == 0) ? W2u : (gateB == 1) ? W2f
                       : (gateB == 2) ? W2o : W2c;
    // src float offset for chunk c: ((c*16 + pB)*1024 + j0)*2 + 4*seg
    const float* wSrcBase = W2sel + ((size_t)pB * 1024 + j0) * 2 + (size_t)segB * 4;
    float* const bDst = smem + A_F + gateB * B_GATE + pB * B_STR + segB * 4;

    auto issue = [&](int c) {
        float* sbase = smem + (c % STAGES) * STAGE_F;
        const int k0 = c * BK;
        const float* s = (k0 < EDIM) ? (aSrcIn + k0) : (aSrcH + (k0 - EDIM));
        float* aD = aDst0 + (c % STAGES) * STAGE_F;
        cp16(aD,      s + aSeg * 4);
        cp16(aD + 16, s + (aSeg + 4) * 4);
        (void)sbase;
        const float* ws = wSrcBase + (size_t)c * (16 * 2048);
        float* wd = bDst + (c % STAGES) * STAGE_F;
        #pragma unroll
        for (int q = 0; q < 4; q++) cp16(wd + q * 4, ws + q * 4);
        cp_commit();
    };

    auto compute = [&](int slot) {
        const float* sA  = smem + slot * STAGE_F;
        const float* sBg = sA + A_F + wx * B_GATE;
        #pragma unroll
        for (int q = 0; q < 4; q++) {
            float2 A0[2], A1[2];
            #pragma unroll
            for (int mi = 0; mi < 2; mi++) {
                const float* pa = sA + (32 * wy + 16 * mi + g4) * A_STR
                                + (4 * q + t4) * 2;
                A0[mi] = *(const float2*)pa;                 // a0 (k=8q+t4), a2 (k+4)
                A1[mi] = *(const float2*)(pa + 8 * A_STR);   // a1, a3 (row+8)
            }
            #pragma unroll
            for (int ni = 0; ni < 4; ni++) {
                const float2 Bf = *(const float2*)(sBg + ((4 * q + t4) * B_STR
                                                          + (8 * ni + g4) * 2));
                const uint32_t b0 = __float_as_uint(Bf.x);
                const uint32_t b1 = __float_as_uint(Bf.y);
                mma_tf32(acc[0][ni],
                         __float_as_uint(A0[0].x), __float_as_uint(A1[0].x),
                         __float_as_uint(A0[0].y), __float_as_uint(A1[0].y), b0, b1);
                mma_tf32(acc[1][ni],
                         __float_as_uint(A0[1].x), __float_as_uint(A1[1].x),
                         __float_as_uint(A0[1].y), __float_as_uint(A1[1].y), b0, b1);
            }
        }
    };

    issue(0);
    issue(1);
    #pragma unroll 1
    for (int c = 0; c < KT2; c++) {
        cp_wait<STAGES - 2>();
        __syncthreads();
        if (c + 2 < KT2) issue(c + 2); else cp_commit();
        compute(c % STAGES);
    }
}

// ---------------------------------------------------------------------------
// Wave kernel: all cells (l, t) with l + t == w. grid = (32 jblk, 4 bblk, cells).
// ---------------------------------------------------------------------------
#define GS_STRIDE 130

__global__ __launch_bounds__(256, 2)
void lstm_wave(int w, int l_lo,
               const float* __restrict__ hwPrev, float* __restrict__ hwCur,
               const float* __restrict__ xr, const float* __restrict__ h0r,
               const float* __restrict__ c0,
               const float* __restrict__ W2base,
               const float* __restrict__ bu, const float* __restrict__ bf,
               const float* __restrict__ bo, const float* __restrict__ bc,
               float* __restrict__ crun,
               float* __restrict__ outH, float* __restrict__ outC,
               float* __restrict__ outHt, float* __restrict__ outCt)
{
    extern __shared__ float smem[];
    const int l  = l_lo + blockIdx.z;
    const int t  = w - l;
    const int j0 = blockIdx.x * 32;
    const int b0 = blockIdx.y * BM;

    const float* inA;
    int strideIn;
    if (l == 0) { inA = xr + (size_t)t * EDIM; strideIn = TIME * EDIM; }
    else        { inA = hwPrev + (size_t)(l - 1) * BATCH * HDIM; strideIn = HDIM; }
    const float* hB = (t == 0) ? (h0r + (size_t)l * BATCH * HDIM)
                               : (hwPrev + (size_t)l * BATCH * HDIM);

    const size_t GSZ  = (size_t)LAYERS * KDIM * HDIM;  // per-gate packed size (floats)
    const size_t lOff = (size_t)l * KDIM * HDIM;
    const float* W2u = W2base + lOff;
    const float* W2f = W2base + GSZ + lOff;
    const float* W2o = W2base + 2 * GSZ + lOff;
    const float* W2c = W2base + 3 * GSZ + lOff;

    float acc[2][4][4];
    #pragma unroll
    for (int mi = 0; mi < 2; mi++)
        #pragma unroll
        for (int ni = 0; ni < 4; ni++)
            #pragma unroll
            for (int r = 0; r < 4; r++) acc[mi][ni][r] = 0.0f;

    gemm_k2048(smem, inA, strideIn, hB, b0, W2u, W2f, W2o, W2c, j0, acc);

    cp_wait<0>();
    __syncthreads();

    // Gate exchange through smem: 64 rows x (4 gates x 32 cols)
    float* gs = smem;
    {
        const int lane = threadIdx.x & 31;
        const int warp = threadIdx.x >> 5;
        const int wy = warp >> 2, wx = warp & 3;
        const int g4 = lane >> 2, t4 = lane & 3;
        #pragma unroll
        for (int mi = 0; mi < 2; mi++) {
            #pragma unroll
            for (int ni = 0; ni < 4; ni++) {
                const int row = 32 * wy + 16 * mi + g4;
                const int col = wx * 32 + 8 * ni + 2 * t4;
                *(float2*)(gs + row * GS_STRIDE + col) =
                    make_float2(acc[mi][ni][0], acc[mi][ni][1]);
                *(float2*)(gs + (row + 8) * GS_STRIDE + col) =
                    make_float2(acc[mi][ni][2], acc[mi][ni][3]);
            }
        }
    }
    __syncthreads();

    const int jj = threadIdx.x & 31;
    const int r0 = threadIdx.x >> 5;
    const int j  = j0 + jj;
    // Permuted column for packed-h write: pos(k) = 2*(k&3) + ((k>>2)&1)
    const int j_p = (j & ~7) | ((j & 3) << 1) | ((j >> 2) & 1);
    const float b_u = bu[l * HDIM + j], b_f = bf[l * HDIM + j];
    const float b_o = bo[l * HDIM + j], b_c = bc[l * HDIM + j];

    float* cl = crun + (size_t)l * BATCH * HDIM;
    const float* colds = (t == 0) ? (c0 + (size_t)l * BATCH * HDIM) : cl;
    float* hcur = hwCur + (size_t)l * BATCH * HDIM;
    const bool last = (l == LAYERS - 1);

    #pragma unroll
    for (int i = 0; i < 8; i++) {
        const int row = r0 + 8 * i;
        const int b   = b0 + row;
        const float su = gs[row * GS_STRIDE +      jj] + b_u;
        const float sf = gs[row * GS_STRIDE + 32 + jj] + b_f;
        const float so = gs[row * GS_STRIDE + 64 + jj] + b_o;
        const float sc = gs[row * GS_STRIDE + 96 + jj] + b_c;
        const float u  = 1.0f / (1.0f + expf(-su));
        const float f  = 1.0f / (1.0f + expf(-sf));
        const float o  = 1.0f / (1.0f + expf(-so));
        const float ct = tanhf(sc);
        const size_t idx = (size_t)b * HDIM + j;
        const float c_new = f * colds[idx] + u * ct;
        const float h_new = o * tanhf(c_new);
        cl[idx] = c_new;
        hcur[(size_t)b * HDIM + j_p] = f2tf32f(h_new);   // rounded+permuted: GEMM input
        if (last) {
            const size_t oidx = ((size_t)b * TIME + t) * HDIM + j;
            outH[oidx] = h_new;
            outC[oidx] = c_new;
            if (t == TIME - 1) { outHt[idx] = h_new; outCt[idx] = c_new; }
        }
    }
}

extern "C" void kernel_launch(void* const* d_in, const int* in_sizes, int n_in,
                              void* d_out, int out_size) {
    const float* x  = (const float*)d_in[0];   // (B, T, E)
    const float* h0 = (const float*)d_in[1];   // (L, B, H)
    const float* c0 = (const float*)d_in[2];   // (L, B, H)
    const float* Wu = (const float*)d_in[3];   // (L, 2048, H)
    const float* bu = (const float*)d_in[4];   // (L, H)
    const float* Wf = (const float*)d_in[5];
    const float* bf = (const float*)d_in[6];
    const float* Wo = (const float*)d_in[7];
    const float* bo = (const float*)d_in[8];
    const float* Wc = (const float*)d_in[9];
    const float* bc = (const float*)d_in[10];

    float* out = (float*)d_out;
    float* outHidden = out;                                   // (B, T, H)
    float* outMem    = out + (size_t)BATCH * TIME * HDIM;     // (B, T, H)
    float* outHt     = out + (size_t)2 * BATCH * TIME * HDIM; // (B, 1, H)
    float* outCt     = outHt + (size_t)BATCH * HDIM;          // (B, 1, H)

    float *hwA, *hwB, *crun, *w2, *xr, *h0r;
    cudaGetSymbolAddress((void**)&hwA,  g_hwA);
    cudaGetSymbolAddress((void**)&hwB,  g_hwB);
    cudaGetSymbolAddress((void**)&crun, g_crun);
    cudaGetSymbolAddress((void**)&w2,   g_w2);
    cudaGetSymbolAddress((void**)&xr,   g_xr);
    cudaGetSymbolAddress((void**)&h0r,  g_h0r);

    const size_t GSZ = (size_t)LAYERS * KDIM * HDIM;   // per gate (floats)

    // Prep: round + pack all MMA operands once per launch.
    {
        const size_t wjobs = (size_t)LAYERS * 1024 * 256;  // per gate
        prep_w<<<4096, 256>>>(Wu, w2,           wjobs);
        prep_w<<<4096, 256>>>(Wf, w2 + GSZ,     wjobs);
        prep_w<<<4096, 256>>>(Wo, w2 + 2 * GSZ, wjobs);
        prep_w<<<4096, 256>>>(Wc, w2 + 3 * GSZ, wjobs);
        prep_act<<<1184, 256>>>((const float4*)x,  (float4*)xr,
                                (size_t)BATCH * TIME * EDIM / 8);
        prep_act<<<1184, 256>>>((const float4*)h0, (float4*)h0r,
                                (size_t)LAYERS * BATCH * HDIM / 8);
    }

    const int GSMEM = STAGES * STAGE_F * 4;   // 86016 B
    cudaFuncSetAttribute(lstm_wave, cudaFuncAttributeMaxDynamicSharedMemorySize, GSMEM);

    // Wavefront: wave w runs all cells (l, t) with l + t == w.
    for (int w = 0; w < LAYERS + TIME - 1; w++) {
        const int l_lo  = (w - (TIME - 1) > 0) ? (w - (TIME - 1)) : 0;
        const int l_hi  = (w < LAYERS - 1) ? w : (LAYERS - 1);
        const int cells = l_hi - l_lo + 1;
        const float* hwPrev = (w & 1) ? hwA : hwB;
        float*       hwCur  = (w & 1) ? hwB : hwA;

        const dim3 grid(HDIM / 32, BATCH / BM, cells);
        lstm_wave<<<grid, 256, GSMEM>>>(w, l_lo, hwPrev, hwCur,
                                        xr, h0r, c0, w2,
                                        bu, bf, bo, bc,
                                        crun,
                                        outHidden, outMem, outHt, outCt);
    }
}

// round 15
// speedup vs baseline: 2.0388x; 1.0997x over previous
#include <cuda_runtime.h>
#include <math.h>
#include <stdint.h>

// Problem constants
#define LAYERS 8
#define BATCH  256
#define TIME   8
#define EDIM   1024
#define HDIM   1024
#define KDIM   2048

#define BM     64
#define BK     32
#define KT2    64      // 2048 / BK
#define STAGES 3
#define NCELLS (LAYERS * TIME)
#define CTAS_PER_CELL 128

// Scratch buffers
__device__ float g_hseq[(size_t)LAYERS * TIME * BATCH * HDIM]; // per-(l,t) h, rounded+permuted
__device__ float g_crun[LAYERS * BATCH * HDIM];                // per-layer running cell state
__device__ float g_w2[(size_t)4 * LAYERS * KDIM * HDIM];       // packed weights, 268 MB
__device__ float g_xr[BATCH * TIME * EDIM];                    // rounded+permuted x
__device__ float g_h0r[LAYERS * BATCH * HDIM];                 // rounded+permuted h0
__device__ int   g_cnt[NCELLS];                                // per-cell done counters

__device__ __forceinline__ float f2tf32f(float f) {
    float r;
    asm("{ .reg .b32 t; cvt.rna.tf32.f32 t, %1; mov.b32 %0, t; }" : "=f"(r) : "f"(f));
    return r;
}

__device__ __forceinline__ void mma_tf32(float c[4],
                                         uint32_t a0, uint32_t a1, uint32_t a2, uint32_t a3,
                                         uint32_t b0, uint32_t b1) {
    asm volatile(
        "mma.sync.aligned.m16n8k8.row.col.f32.tf32.tf32.f32 "
        "{%0,%1,%2,%3}, {%4,%5,%6,%7}, {%8,%9}, {%0,%1,%2,%3};"
        : "+f"(c[0]), "+f"(c[1]), "+f"(c[2]), "+f"(c[3])
        : "r"(a0), "r"(a1), "r"(a2), "r"(a3), "r"(b0), "r"(b1));
}

__device__ __forceinline__ void cp16(uint32_t dst, const float* src) {
    asm volatile("cp.async.cg.shared.global [%0], [%1], 16;" :: "r"(dst), "l"(src));
}
__device__ __forceinline__ void cp_commit() {
    asm volatile("cp.async.commit_group;");
}
template <int N> __device__ __forceinline__ void cp_wait() {
    asm volatile("cp.async.wait_group %0;" :: "n"(N));
}

// ---------------------------------------------------------------------------
// Wavefront cell numbering helpers
// ---------------------------------------------------------------------------
__device__ __forceinline__ int cell_index(int l, int t) {
    const int wv = l + t;
    int base = 0;
    for (int w = 0; w < wv; w++) {
        const int l_lo = (w - (TIME - 1) > 0) ? (w - (TIME - 1)) : 0;
        const int l_hi = (w < LAYERS - 1) ? w : (LAYERS - 1);
        base += l_hi - l_lo + 1;
    }
    const int l_lo = (wv - (TIME - 1) > 0) ? (wv - (TIME - 1)) : 0;
    return base + (l - l_lo);
}

__device__ __forceinline__ void cell_decode(int cell, int& l, int& t) {
    int wv = 0, base = 0;
    for (;;) {
        const int l_lo = (wv - (TIME - 1) > 0) ? (wv - (TIME - 1)) : 0;
        const int l_hi = (wv < LAYERS - 1) ? wv : (LAYERS - 1);
        const int n = l_hi - l_lo + 1;
        if (cell < base + n) { l = l_lo + (cell - base); break; }
        base += n; wv++;
    }
    t = wv - l;
}

__device__ __forceinline__ void wait_cell(int cell) {
    volatile int* p = &g_cnt[cell];
    while (*p < CTAS_PER_CELL)
        asm volatile("nanosleep.u32 128;");
}

// ---------------------------------------------------------------------------
// Prep kernels (2 launches).
// Interleaved-pair layout: k-groups of 8 stored as pairs (k, k+4):
// pos(k) = 2*(k&3) + ((k>>2)&1). Fragment pair -> one aligned float2 LDS.
// ---------------------------------------------------------------------------
__global__ __launch_bounds__(256)
void prep_act(const float4* __restrict__ x, float4* __restrict__ xr, size_t n8x,
              const float4* __restrict__ h0, float4* __restrict__ h0r, size_t n8h) {
    size_t i = (size_t)blockIdx.x * blockDim.x + threadIdx.x;
    const size_t stride = (size_t)gridDim.x * blockDim.x;
    const size_t total = n8x + n8h;
    for (; i < total; i += stride) {
        const float4* s = (i < n8x) ? (x + 2 * i) : (h0 + 2 * (i - n8x));
        float4* d       = (i < n8x) ? (xr + 2 * i) : (h0r + 2 * (i - n8x));
        float4 a = s[0];
        float4 b = s[1];
        d[0] = make_float4(f2tf32f(a.x), f2tf32f(b.x), f2tf32f(a.y), f2tf32f(b.y));
        d[1] = make_float4(f2tf32f(a.z), f2tf32f(b.z), f2tf32f(a.w), f2tf32f(b.w));
    }
}

// All 4 gates in one launch. W[g][l][k][j] -> W2 float2 pairs (W[k_lo][j],
// W[k_lo+4][j]), kp = (k_lo>>3)*4 + (k_lo&3), tf32-rounded.
__global__ __launch_bounds__(256)
void prep_w(const float* __restrict__ Wu, const float* __restrict__ Wf,
            const float* __restrict__ Wo, const float* __restrict__ Wc,
            float* __restrict__ W2, size_t njobs) {
    const size_t GSZ = (size_t)LAYERS * KDIM * HDIM;
    size_t i = (size_t)blockIdx.x * blockDim.x + threadIdx.x;
    const size_t stride = (size_t)gridDim.x * blockDim.x;
    for (; i < njobs; i += stride) {
        const int j4 = (int)(i & 255) * 4;
        const int kp = (int)(i >> 8) & 1023;
        const int l  = (int)(i >> 18) & 7;
        const int g  = (int)(i >> 21);
        const int k_lo = (kp >> 2) * 8 + (kp & 3);
        const float* W = (g == 0) ? Wu : (g == 1) ? Wf : (g == 2) ? Wo : Wc;
        const float* src = W + ((size_t)l * KDIM + k_lo) * HDIM + j4;
        float4 lo = *(const float4*)src;
        float4 hi = *(const float4*)(src + 4 * HDIM);
        float* d = W2 + (size_t)g * GSZ + ((size_t)l * 1024 + kp) * 2048 + (size_t)j4 * 2;
        *(float4*)d       = make_float4(f2tf32f(lo.x), f2tf32f(hi.x),
                                        f2tf32f(lo.y), f2tf32f(hi.y));
        *(float4*)(d + 4) = make_float4(f2tf32f(lo.z), f2tf32f(hi.z),
                                        f2tf32f(lo.w), f2tf32f(hi.w));
    }
}

// -----------------------------------------------------------------------------
// GEMM mainloop, K = 2048 = [input 1024 | h 1024], float2-fragment loads.
// A tile: 64 rows x 32 floats (pair-interleaved), row stride 40 floats.
// B tile: 4 gates x 16 pair-rows x 32 float2, pair-row stride 72 floats.
// -----------------------------------------------------------------------------
#define A_STR   40
#define B_STR   72
#define A_F     (64 * A_STR)               // 2560 floats
#define B_GATE  (16 * B_STR)               // 1152 floats
#define STAGE_F (A_F + 4 * B_GATE)         // 7168 floats

__device__ __forceinline__ void gemm_k2048(
    float* smem,
    const float* __restrict__ inA, int strideIn,      // k in [0,1024), packed rows
    const float* __restrict__ hB,                     // k in [1024,2048), stride HDIM
    int r0,
    const float* __restrict__ W2u, const float* __restrict__ W2f,
    const float* __restrict__ W2o, const float* __restrict__ W2c, // per-layer packed
    int j0, float acc[2][4][4])
{
    const int tid  = threadIdx.x;
    const int lane = tid & 31;
    const int warp = tid >> 5;
    const int wy   = warp >> 2;
    const int wx   = warp & 3;
    const int g4   = lane >> 2;
    const int t4   = lane & 3;

    // A cp.async mapping: 64 rows x 8 segs(16B); 2 segs/thread
    const int aRow = tid >> 2;
    const int aSeg = tid & 3;
    const float* aSrcIn = inA + (size_t)(r0 + aRow) * strideIn;
    const float* aSrcH  = hB  + (size_t)(r0 + aRow) * HDIM;
    float* const aDst0 = smem + aRow * A_STR + aSeg * 4;

    // B cp.async mapping: 64 (gate,prow) x 16 segs(16B); 4 segs/thread
    const int prow_g = tid >> 2;             // 0..63 = gate*16 + p
    const int gateB  = prow_g >> 4;
    const int pB     = prow_g & 15;
    const int segB   = (tid & 3) * 4;
    const float* W2sel = (gateB == 0) ? W2u : (gateB == 1) ? W2f
                       : (gateB == 2) ? W2o : W2c;
    const float* wSrcBase = W2sel + ((size_t)pB * 1024 + j0) * 2 + (size_t)segB * 4;
    float* const bDst = smem + A_F + gateB * B_GATE + pB * B_STR + segB * 4;

    auto issue = [&](int c) {
        const int k0 = c * BK;
        const float* s = (k0 < EDIM) ? (aSrcIn + k0) : (aSrcH + (k0 - EDIM));
        float* aD = aDst0 + (c % STAGES) * STAGE_F;
        cp16((uint32_t)__cvta_generic_to_shared(aD),      s + aSeg * 4);
        cp16((uint32_t)__cvta_generic_to_shared(aD + 16), s + (aSeg + 4) * 4);
        const float* ws = wSrcBase + (size_t)c * (16 * 2048);
        float* wd = bDst + (c % STAGES) * STAGE_F;
        #pragma unroll
        for (int q = 0; q < 4; q++)
            cp16((uint32_t)__cvta_generic_to_shared(wd + q * 4), ws + q * 4);
        cp_commit();
    };

    auto compute = [&](int slot) {
        const float* sA  = smem + slot * STAGE_F;
        const float* sBg = sA + A_F + wx * B_GATE;
        #pragma unroll
        for (int q = 0; q < 4; q++) {
            float2 A0[2], A1[2];
            #pragma unroll
            for (int mi = 0; mi < 2; mi++) {
                const float* pa = sA + (32 * wy + 16 * mi + g4) * A_STR
                                + (4 * q + t4) * 2;
                A0[mi] = *(const float2*)pa;
                A1[mi] = *(const float2*)(pa + 8 * A_STR);
            }
            #pragma unroll
            for (int ni = 0; ni < 4; ni++) {
                const float2 Bf = *(const float2*)(sBg + ((4 * q + t4) * B_STR
                                                          + (8 * ni + g4) * 2));
                const uint32_t b0 = __float_as_uint(Bf.x);
                const uint32_t b1 = __float_as_uint(Bf.y);
                mma_tf32(acc[0][ni],
                         __float_as_uint(A0[0].x), __float_as_uint(A1[0].x),
                         __float_as_uint(A0[0].y), __float_as_uint(A1[0].y), b0, b1);
                mma_tf32(acc[1][ni],
                         __float_as_uint(A0[1].x), __float_as_uint(A1[1].x),
                         __float_as_uint(A0[1].y), __float_as_uint(A1[1].y), b0, b1);
            }
        }
    };

    issue(0);
    issue(1);
    #pragma unroll 1
    for (int c = 0; c < KT2; c++) {
        cp_wait<STAGES - 2>();
        __syncthreads();
        if (c + 2 < KT2) issue(c + 2); else cp_commit();
        compute(c % STAGES);
    }
}

// ---------------------------------------------------------------------------
// Fused DAG kernel: 64 cells x 128 CTAs, topological (wavefront) blockIdx
// order; device-side flags enforce (l-1,t) and (l,t-1) dependencies.
// ---------------------------------------------------------------------------
#define GS_STRIDE 130

__global__ __launch_bounds__(256, 2)
void lstm_fused(const float* __restrict__ xr, const float* __restrict__ h0r,
                const float* __restrict__ c0,
                const float* __restrict__ w2,
                const float* __restrict__ bu, const float* __restrict__ bf,
                const float* __restrict__ bo, const float* __restrict__ bc,
                float* __restrict__ crun, float* __restrict__ hseq,
                float* __restrict__ outH, float* __restrict__ outC,
                float* __restrict__ outHt, float* __restrict__ outCt)
{
    extern __shared__ float smem[];
    const int cell = blockIdx.x >> 7;
    const int tile = blockIdx.x & 127;
    const int j0 = (tile & 31) * 32;
    const int b0 = (tile >> 5) * BM;
    const int tid = threadIdx.x;

    int l, t;
    cell_decode(cell, l, t);

    // Wait for producers (thread 0 spins; nanosleep backoff).
    if (tid == 0) {
        if (l > 0) wait_cell(cell_index(l - 1, t));
        if (t > 0) wait_cell(cell_index(l, t - 1));
        __threadfence();
    }
    __syncthreads();

    // Cell operand pointers
    const float* inA; int strideIn;
    if (l == 0) { inA = xr + (size_t)t * EDIM; strideIn = TIME * EDIM; }
    else {
        inA = hseq + ((size_t)(l - 1) * TIME + t) * BATCH * HDIM;
        strideIn = HDIM;
    }
    const float* hB = (t == 0) ? (h0r + (size_t)l * BATCH * HDIM)
                               : (hseq + ((size_t)l * TIME + (t - 1)) * BATCH * HDIM);
    const size_t GSZ  = (size_t)LAYERS * KDIM * HDIM;
    const size_t lOff = (size_t)l * KDIM * HDIM;

    float acc[2][4][4];
    #pragma unroll
    for (int mi = 0; mi < 2; mi++)
        #pragma unroll
        for (int ni = 0; ni < 4; ni++)
            #pragma unroll
            for (int r = 0; r < 4; r++) acc[mi][ni][r] = 0.0f;

    gemm_k2048(smem, inA, strideIn, hB, b0,
               w2 + lOff, w2 + GSZ + lOff, w2 + 2 * GSZ + lOff, w2 + 3 * GSZ + lOff,
               j0, acc);

    cp_wait<0>();
    __syncthreads();

    // Gate exchange through smem: 64 rows x (4 gates x 32 cols)
    float* gs = smem;
    {
        const int lane = tid & 31;
        const int warp = tid >> 5;
        const int wy = warp >> 2, wx = warp & 3;
        const int g4 = lane >> 2, t4 = lane & 3;
        #pragma unroll
        for (int mi = 0; mi < 2; mi++) {
            #pragma unroll
            for (int ni = 0; ni < 4; ni++) {
                const int row = 32 * wy + 16 * mi + g4;
                const int col = wx * 32 + 8 * ni + 2 * t4;
                *(float2*)(gs + row * GS_STRIDE + col) =
                    make_float2(acc[mi][ni][0], acc[mi][ni][1]);
                *(float2*)(gs + (row + 8) * GS_STRIDE + col) =
                    make_float2(acc[mi][ni][2], acc[mi][ni][3]);
            }
        }
    }
    __syncthreads();

    const int jj = tid & 31;
    const int r0 = tid >> 5;
    const int j  = j0 + jj;
    // Permuted column for packed-h write: pos(k) = 2*(k&3) + ((k>>2)&1)
    const int j_p = (j & ~7) | ((j & 3) << 1) | ((j >> 2) & 1);
    const float b_u = bu[l * HDIM + j], b_f = bf[l * HDIM + j];
    const float b_o = bo[l * HDIM + j], b_c = bc[l * HDIM + j];

    float* cl = crun + (size_t)l * BATCH * HDIM;
    const float* colds = (t == 0) ? (c0 + (size_t)l * BATCH * HDIM) : cl;
    float* hdst = hseq + ((size_t)l * TIME + t) * BATCH * HDIM;
    const bool last = (l == LAYERS - 1);

    #pragma unroll
    for (int i = 0; i < 8; i++) {
        const int row = r0 + 8 * i;
        const int b   = b0 + row;
        const float su = gs[row * GS_STRIDE +      jj] + b_u;
        const float sf = gs[row * GS_STRIDE + 32 + jj] + b_f;
        const float so = gs[row * GS_STRIDE + 64 + jj] + b_o;
        const float sc = gs[row * GS_STRIDE + 96 + jj] + b_c;
        const float u  = 1.0f / (1.0f + expf(-su));
        const float f  = 1.0f / (1.0f + expf(-sf));
        const float o  = 1.0f / (1.0f + expf(-so));
        const float ct = tanhf(sc);
        const size_t idx = (size_t)b * HDIM + j;
        const float c_new = f * colds[idx] + u * ct;
        const float h_new = o * tanhf(c_new);
        cl[idx] = c_new;
        hdst[(size_t)b * HDIM + j_p] = f2tf32f(h_new);
        if (last) {
            const size_t oidx = ((size_t)b * TIME + t) * HDIM + j;
            outH[oidx] = h_new;
            outC[oidx] = c_new;
            if (t == TIME - 1) { outHt[idx] = h_new; outCt[idx] = c_new; }
        }
    }

    // Publish: all writes visible, then bump this cell's counter.
    __threadfence();
    __syncthreads();
    if (tid == 0) atomicAdd(&g_cnt[cell], 1);
}

extern "C" void kernel_launch(void* const* d_in, const int* in_sizes, int n_in,
                              void* d_out, int out_size) {
    const float* x  = (const float*)d_in[0];   // (B, T, E)
    const float* h0 = (const float*)d_in[1];   // (L, B, H)
    const float* c0 = (const float*)d_in[2];   // (L, B, H)
    const float* Wu = (const float*)d_in[3];   // (L, 2048, H)
    const float* bu = (const float*)d_in[4];   // (L, H)
    const float* Wf = (const float*)d_in[5];
    const float* bf = (const float*)d_in[6];
    const float* Wo = (const float*)d_in[7];
    const float* bo = (const float*)d_in[8];
    const float* Wc = (const float*)d_in[9];
    const float* bc = (const float*)d_in[10];

    float* out = (float*)d_out;
    float* outHidden = out;                                   // (B, T, H)
    float* outMem    = out + (size_t)BATCH * TIME * HDIM;     // (B, T, H)
    float* outHt     = out + (size_t)2 * BATCH * TIME * HDIM; // (B, 1, H)
    float* outCt     = outHt + (size_t)BATCH * HDIM;          // (B, 1, H)

    float *hseq, *crun, *w2, *xr, *h0r;
    int* cnt;
    cudaGetSymbolAddress((void**)&hseq, g_hseq);
    cudaGetSymbolAddress((void**)&crun, g_crun);
    cudaGetSymbolAddress((void**)&w2,   g_w2);
    cudaGetSymbolAddress((void**)&xr,   g_xr);
    cudaGetSymbolAddress((void**)&h0r,  g_h0r);
    cudaGetSymbolAddress((void**)&cnt,  g_cnt);

    // Reset dependency counters (capture-legal memset node).
    cudaMemsetAsync(cnt, 0, NCELLS * sizeof(int), 0);

    // Prep: pack weights + round/permute activations.
    prep_w<<<16384, 256>>>(Wu, Wf, Wo, Wc, w2, (size_t)4 * LAYERS * 1024 * 256);
    prep_act<<<2048, 256>>>((const float4*)x,  (float4*)xr,
                            (size_t)BATCH * TIME * EDIM / 8,
                            (const float4*)h0, (float4*)h0r,
                            (size_t)LAYERS * BATCH * HDIM / 8);

    const int GSMEM = STAGES * STAGE_F * 4;   // 86016 B
    cudaFuncSetAttribute(lstm_fused, cudaFuncAttributeMaxDynamicSharedMemorySize, GSMEM);

    // Single DAG launch: 64 cells x 128 CTAs in wavefront order.
    lstm_fused<<<NCELLS * CTAS_PER_CELL, 256, GSMEM>>>(
        xr, h0r, c0, w2, bu, bf, bo, bc,
        crun, hseq, outHidden, outMem, outHt, outCt);
}